// round 5
// baseline (speedup 1.0000x reference)
#include <cuda_runtime.h>

#define NB 4
#define NT 1024
#define NH 16
#define NS 64
#define NE 1024
#define NEGV -1000000000.0f

// Scratch (device globals — allocation-free kernel_launch)
static __device__ float g_Q[NB*NH*NT*NS];
static __device__ float g_K[NB*NH*NT*NS];
static __device__ float g_V[NB*NH*NT*NS];
static __device__ float g_QEr[(size_t)NB*NH*NT*NT];   // only upper band used
static __device__ float g_attn[NB*NT*NE];             // reference's scrambled layout
static __device__ float g_vmean[NB*NH*NS];

// ---------------------------------------------------------------------------
// K1: QKV projection.  x viewed as [65536,64], row r = (b*T+t)*H + h.
// ---------------------------------------------------------------------------
__global__ __launch_bounds__(256) void proj_kernel(
    const float* __restrict__ x, const float* __restrict__ Wq,
    const float* __restrict__ Wk, const float* __restrict__ Wv)
{
    __shared__ float As[4096];
    __shared__ float Bs[4096];
    const int tid = threadIdx.x;
    const int tx = tid & 15, ty = tid >> 4;
    const int m0 = blockIdx.x * 64;

    {
        const float4* src = (const float4*)(x + (size_t)m0 * 64);
        float4* dst = (float4*)As;
        for (int i = tid; i < 1024; i += 256) dst[i] = src[i];
    }

    const float* Ws[3] = {Wq, Wk, Wv};
    float* Os[3] = {g_Q, g_K, g_V};

    for (int w = 0; w < 3; w++) {
        __syncthreads();
        {   // Bs[k*64+o] = W[o*64+k]  (transposed)
            const int o  = tid >> 2;
            const int k0 = (tid & 3) * 16;
            const float* wp = Ws[w] + o * 64 + k0;
            #pragma unroll
            for (int u = 0; u < 4; u++) {
                float4 v = *(const float4*)(wp + u * 4);
                Bs[(k0 + u*4 + 0) * 64 + o] = v.x;
                Bs[(k0 + u*4 + 1) * 64 + o] = v.y;
                Bs[(k0 + u*4 + 2) * 64 + o] = v.z;
                Bs[(k0 + u*4 + 3) * 64 + o] = v.w;
            }
        }
        __syncthreads();
        float acc[4][4] = {};
        #pragma unroll 4
        for (int k = 0; k < 64; k++) {
            float a[4];
            #pragma unroll
            for (int i = 0; i < 4; i++) a[i] = As[(ty*4 + i)*64 + k];
            float4 bv = *(const float4*)(Bs + k*64 + tx*4);
            #pragma unroll
            for (int i = 0; i < 4; i++) {
                acc[i][0] += a[i]*bv.x; acc[i][1] += a[i]*bv.y;
                acc[i][2] += a[i]*bv.z; acc[i][3] += a[i]*bv.w;
            }
        }
        #pragma unroll
        for (int i = 0; i < 4; i++) {
            const int r = m0 + ty*4 + i;
            const int h = r & 15, t = (r >> 4) & 1023, b = r >> 14;
            float* dst = Os[w] + (((size_t)(b*NH + h))*NT + t)*NS + tx*4;
            *(float4*)dst = make_float4(acc[i][0], acc[i][1], acc[i][2], acc[i][3]);
        }
    }
}

// ---------------------------------------------------------------------------
// K2: per-(b,h) mean of V over all t (padded rows: softmax exactly uniform)
// ---------------------------------------------------------------------------
__global__ __launch_bounds__(64) void vmean_kernel()
{
    const int bh = blockIdx.x;
    const int o  = threadIdx.x;
    const float* vp = g_V + (size_t)bh * NT * NS + o;
    float sum = 0.f;
    for (int t = 0; t < NT; t++) sum += vp[(size_t)t * NS];
    g_vmean[bh * NS + o] = sum * (1.0f / 1024.0f);
}

// ---------------------------------------------------------------------------
// K3: QEr[b,h,tq,l] = Q[b,h,tq,:] . Er[h,l,:]  (band l >= 1023-tq only)
// ---------------------------------------------------------------------------
__global__ __launch_bounds__(256) void qer_kernel(const float* __restrict__ Er)
{
    const int n0 = blockIdx.x * 64;
    const int m0 = blockIdx.y * 64;
    if (m0 + n0 < 897) return;            // never-read band: skip
    const int bh = blockIdx.z;
    const int h  = bh & 15;
    __shared__ float As[4096];
    __shared__ float Bs[4096];
    const int tid = threadIdx.x;
    const int tx = tid & 15, ty = tid >> 4;

    {
        const float4* src = (const float4*)(g_Q + ((size_t)bh*NT + m0)*NS);
        float4* dst = (float4*)As;
        for (int i = tid; i < 1024; i += 256) dst[i] = src[i];
    }
    {
        const int n  = tid >> 2;
        const int k0 = (tid & 3) * 16;
        const float* ep = Er + ((size_t)h*NT + n0 + n)*NS + k0;
        #pragma unroll
        for (int u = 0; u < 4; u++) {
            float4 v = *(const float4*)(ep + u*4);
            Bs[(k0+u*4+0)*64 + n] = v.x;
            Bs[(k0+u*4+1)*64 + n] = v.y;
            Bs[(k0+u*4+2)*64 + n] = v.z;
            Bs[(k0+u*4+3)*64 + n] = v.w;
        }
    }
    __syncthreads();
    float acc[4][4] = {};
    #pragma unroll 4
    for (int k = 0; k < 64; k++) {
        float a[4];
        #pragma unroll
        for (int i = 0; i < 4; i++) a[i] = As[(ty*4 + i)*64 + k];
        float4 bv = *(const float4*)(Bs + k*64 + tx*4);
        #pragma unroll
        for (int i = 0; i < 4; i++) {
            acc[i][0] += a[i]*bv.x; acc[i][1] += a[i]*bv.y;
            acc[i][2] += a[i]*bv.z; acc[i][3] += a[i]*bv.w;
        }
    }
    #pragma unroll
    for (int i = 0; i < 4; i++) {
        const int tq = m0 + ty*4 + i;
        *(float4*)(g_QEr + ((size_t)bh*NT + tq)*NT + n0 + tx*4) =
            make_float4(acc[i][0], acc[i][1], acc[i][2], acc[i][3]);
    }
}

// ---------------------------------------------------------------------------
// K4: flash-style causal attention + relative bias + online softmax.
// scores = (q.k)/32 + QEr[tq, 1023 - tq + tk]; causal NEG; pad rows -> vmean.
// EPILOGUE writes the reference's (bths -> transpose -> reshape) scrambled
// layout: attn value (b,h,tq,s) lands at row h*64 + tq/16, col (tq%16)*64+s.
// ---------------------------------------------------------------------------
__global__ __launch_bounds__(256) void attn_kernel(const int* __restrict__ mask)
{
    const int bh = blockIdx.y;
    const int m0 = blockIdx.x * 64;
    const int b = bh >> 4, h = bh & 15;
    __shared__ float Qs[4096];
    __shared__ float KVs[4096];   // K^T during S-compute, V during PV
    __shared__ float Ps[4096];
    const int tid = threadIdx.x;
    const int tx = tid & 15, ty = tid >> 4;

    {
        const float4* src = (const float4*)(g_Q + ((size_t)bh*NT + m0)*NS);
        float4* dst = (float4*)Qs;
        for (int i = tid; i < 1024; i += 256) dst[i] = src[i];
    }

    float mrow[4], lrow[4], O[4][4];
    #pragma unroll
    for (int i = 0; i < 4; i++) {
        mrow[i] = -1e30f; lrow[i] = 0.f;
        #pragma unroll
        for (int j = 0; j < 4; j++) O[i][j] = 0.f;
    }

    for (int kt = 0; kt <= (int)blockIdx.x; kt++) {
        const int n0 = kt * 64;
        __syncthreads();
        {   // KVs[k*64+c] = K[bh, n0+c, k]  (transposed)
            const int c  = tid >> 2;
            const int k0 = (tid & 3) * 16;
            const float* kp = g_K + ((size_t)bh*NT + n0 + c)*NS + k0;
            #pragma unroll
            for (int u = 0; u < 4; u++) {
                float4 v = *(const float4*)(kp + u*4);
                KVs[(k0+u*4+0)*64 + c] = v.x;
                KVs[(k0+u*4+1)*64 + c] = v.y;
                KVs[(k0+u*4+2)*64 + c] = v.z;
                KVs[(k0+u*4+3)*64 + c] = v.w;
            }
        }
        __syncthreads();

        float s[4][4] = {};
        #pragma unroll 4
        for (int k = 0; k < 64; k++) {
            float a[4];
            #pragma unroll
            for (int i = 0; i < 4; i++) a[i] = Qs[(ty*4 + i)*64 + k];
            float4 bv = *(const float4*)(KVs + k*64 + tx*4);
            #pragma unroll
            for (int i = 0; i < 4; i++) {
                s[i][0] += a[i]*bv.x; s[i][1] += a[i]*bv.y;
                s[i][2] += a[i]*bv.z; s[i][3] += a[i]*bv.w;
            }
        }

        const float inv = 0.03125f;            // 1/sqrt(1024) = 1/32
        #pragma unroll
        for (int i = 0; i < 4; i++) {
            const int tq = m0 + ty*4 + i;
            const float* qer_row = g_QEr + ((size_t)bh*NT + tq)*NT + (1023 - tq);
            #pragma unroll
            for (int j = 0; j < 4; j++) {
                const int tk = n0 + tx*4 + j;
                if (tk > tq) s[i][j] = NEGV;
                else         s[i][j] = fmaf(s[i][j], inv, qer_row[tk]);
            }
        }

        #pragma unroll
        for (int i = 0; i < 4; i++) {
            float rm = fmaxf(fmaxf(s[i][0], s[i][1]), fmaxf(s[i][2], s[i][3]));
            #pragma unroll
            for (int o = 8; o >= 1; o >>= 1)
                rm = fmaxf(rm, __shfl_xor_sync(0xffffffffu, rm, o, 16));
            const float mn = fmaxf(mrow[i], rm);
            const float alpha = __expf(mrow[i] - mn);
            mrow[i] = mn;
            float rs = 0.f;
            #pragma unroll
            for (int j = 0; j < 4; j++) {
                s[i][j] = __expf(s[i][j] - mn);
                rs += s[i][j];
            }
            #pragma unroll
            for (int o = 8; o >= 1; o >>= 1)
                rs += __shfl_xor_sync(0xffffffffu, rs, o, 16);
            lrow[i] = lrow[i]*alpha + rs;
            #pragma unroll
            for (int j = 0; j < 4; j++) O[i][j] *= alpha;
            #pragma unroll
            for (int j = 0; j < 4; j++) Ps[(ty*4+i)*64 + tx*4 + j] = s[i][j];
        }
        __syncthreads();
        {   // overwrite KVs with V tile (row-major)
            const float4* src = (const float4*)(g_V + ((size_t)bh*NT + n0)*NS);
            float4* dst = (float4*)KVs;
            for (int i = tid; i < 1024; i += 256) dst[i] = src[i];
        }
        __syncthreads();
        #pragma unroll 4
        for (int c = 0; c < 64; c++) {
            float4 vv = *(const float4*)(KVs + c*64 + tx*4);
            float p[4];
            #pragma unroll
            for (int i = 0; i < 4; i++) p[i] = Ps[(ty*4+i)*64 + c];
            #pragma unroll
            for (int i = 0; i < 4; i++) {
                O[i][0] += p[i]*vv.x; O[i][1] += p[i]*vv.y;
                O[i][2] += p[i]*vv.z; O[i][3] += p[i]*vv.w;
            }
        }
    }

    #pragma unroll
    for (int i = 0; i < 4; i++) {
        const int tq = m0 + ty*4 + i;
        float4 o4;
        if (mask[b*NT + tq] == 0) {            // padded row: exact uniform softmax
            const float* vm = g_vmean + bh*NS + tx*4;
            o4 = make_float4(vm[0], vm[1], vm[2], vm[3]);
        } else {
            const float invl = 1.0f / lrow[i];
            o4 = make_float4(O[i][0]*invl, O[i][1]*invl, O[i][2]*invl, O[i][3]*invl);
        }
        // Reference layout: (b,h,t,s) flattened as (b, t_new=h*64+t/16, c=(t%16)*64+s)
        const int rnew = h * 64 + (tq >> 4);
        const int cnew = (tq & 15) * 64 + tx * 4;
        *(float4*)(g_attn + ((size_t)(b*NT + rnew))*NE + cnew) = o4;
    }
}

// ---------------------------------------------------------------------------
// K5: out = attn @ Wo^T + bo   (M=4096, N=1024, K=1024)
// ---------------------------------------------------------------------------
__global__ __launch_bounds__(256) void out_kernel(
    const float* __restrict__ Wo, const float* __restrict__ bo,
    float* __restrict__ out)
{
    const int n0 = blockIdx.x * 64;
    const int m0 = blockIdx.y * 64;
    __shared__ float As[4096];
    __shared__ float Bs[4096];
    const int tid = threadIdx.x;
    const int tx = tid & 15, ty = tid >> 4;
    float acc[4][4] = {};

    for (int kc = 0; kc < 16; kc++) {
        __syncthreads();
        {
            const int mr = tid >> 2;
            const int k0 = (tid & 3) * 16;
            const float* ap = g_attn + (size_t)(m0 + mr)*NE + kc*64 + k0;
            float4* dst = (float4*)(As + mr*64 + k0);
            #pragma unroll
            for (int u = 0; u < 4; u++) dst[u] = ((const float4*)ap)[u];
        }
        {
            const int n  = tid >> 2;
            const int k0 = (tid & 3) * 16;
            const float* wp = Wo + (size_t)(n0 + n)*NE + kc*64 + k0;
            #pragma unroll
            for (int u = 0; u < 4; u++) {
                float4 v = *(const float4*)(wp + u*4);
                Bs[(k0+u*4+0)*64 + n] = v.x;
                Bs[(k0+u*4+1)*64 + n] = v.y;
                Bs[(k0+u*4+2)*64 + n] = v.z;
                Bs[(k0+u*4+3)*64 + n] = v.w;
            }
        }
        __syncthreads();
        #pragma unroll 4
        for (int k = 0; k < 64; k++) {
            float a[4];
            #pragma unroll
            for (int i = 0; i < 4; i++) a[i] = As[(ty*4 + i)*64 + k];
            float4 bv = *(const float4*)(Bs + k*64 + tx*4);
            #pragma unroll
            for (int i = 0; i < 4; i++) {
                acc[i][0] += a[i]*bv.x; acc[i][1] += a[i]*bv.y;
                acc[i][2] += a[i]*bv.z; acc[i][3] += a[i]*bv.w;
            }
        }
    }
    float4 bb = *(const float4*)(bo + n0 + tx*4);
    #pragma unroll
    for (int i = 0; i < 4; i++) {
        float* dst = out + (size_t)(m0 + ty*4 + i)*NE + n0 + tx*4;
        *(float4*)dst = make_float4(acc[i][0]+bb.x, acc[i][1]+bb.y,
                                    acc[i][2]+bb.z, acc[i][3]+bb.w);
    }
}

// ---------------------------------------------------------------------------
extern "C" void kernel_launch(void* const* d_in, const int* in_sizes, int n_in,
                              void* d_out, int out_size)
{
    const float* x    = (const float*)d_in[0];
    const int*   mask = (const int*)  d_in[1];
    const float* Wq   = (const float*)d_in[2];
    const float* Wk   = (const float*)d_in[3];
    const float* Wv   = (const float*)d_in[4];
    const float* Er   = (const float*)d_in[5];
    const float* Wo   = (const float*)d_in[6];
    const float* bo   = (const float*)d_in[7];
    float* out = (float*)d_out;

    proj_kernel<<<1024, 256>>>(x, Wq, Wk, Wv);
    vmean_kernel<<<64, 64>>>();
    qer_kernel<<<dim3(16, 16, 64), 256>>>(Er);
    attn_kernel<<<dim3(16, 64), 256>>>(mask);
    out_kernel<<<dim3(16, 64), 256>>>(Wo, bo, out);
}

// round 10
// speedup vs baseline: 1.3109x; 1.3109x over previous
#include <cuda_runtime.h>

#define NB 4
#define NT 1024
#define NH 16
#define NS 64
#define NE 1024
#define NEGV -1000000000.0f

// Scratch (device globals — allocation-free kernel_launch)
static __device__ float g_Q[NB*NH*NT*NS];
static __device__ float g_K[NB*NH*NT*NS];
static __device__ float g_V[NB*NH*NT*NS];
static __device__ float g_QEr[(size_t)NB*NH*NT*NT];   // only upper band used
static __device__ float g_attn[NB*NT*NE];             // reference's scrambled layout
static __device__ float g_vmean[NB*NH*NS];

// ---------------------------------------------------------------------------
// K1: QKV projection.  x viewed as [65536,64], row r = (b*T+t)*H + h.
// A stored transposed in smem: As_t[k*64+m]; inner loop = 2xLDS128 / 16 FFMA.
// ---------------------------------------------------------------------------
__global__ __launch_bounds__(256) void proj_kernel(
    const float* __restrict__ x, const float* __restrict__ Wq,
    const float* __restrict__ Wk, const float* __restrict__ Wv)
{
    __shared__ float As[4096];   // transposed: As[k*64+m]
    __shared__ float Bs[4096];   // transposed: Bs[k*64+o]
    const int tid = threadIdx.x;
    const int tx = tid & 15, ty = tid >> 4;
    const int m0 = blockIdx.x * 64;
    const int mr = tid >> 2, k0 = (tid & 3) * 16;

    {   // x tile -> As transposed
        const float* xp = x + (size_t)(m0 + mr) * 64 + k0;
        #pragma unroll
        for (int u = 0; u < 4; u++) {
            float4 v = *(const float4*)(xp + u*4);
            As[(k0+u*4+0)*64 + mr] = v.x;
            As[(k0+u*4+1)*64 + mr] = v.y;
            As[(k0+u*4+2)*64 + mr] = v.z;
            As[(k0+u*4+3)*64 + mr] = v.w;
        }
    }

    const float* Ws[3] = {Wq, Wk, Wv};
    float* Os[3] = {g_Q, g_K, g_V};

    for (int w = 0; w < 3; w++) {
        float4 breg[4];
        {   // prefetch W (row o = mr, cols k0..k0+15)
            const float* wp = Ws[w] + mr * 64 + k0;
            #pragma unroll
            for (int u = 0; u < 4; u++) breg[u] = *(const float4*)(wp + u*4);
        }
        __syncthreads();                        // prior-iter Bs reads done (and As ready)
        #pragma unroll
        for (int u = 0; u < 4; u++) {
            Bs[(k0+u*4+0)*64 + mr] = breg[u].x;
            Bs[(k0+u*4+1)*64 + mr] = breg[u].y;
            Bs[(k0+u*4+2)*64 + mr] = breg[u].z;
            Bs[(k0+u*4+3)*64 + mr] = breg[u].w;
        }
        __syncthreads();
        float acc[4][4] = {};
        #pragma unroll 8
        for (int k = 0; k < 64; k++) {
            float4 a4 = *(const float4*)(As + k*64 + ty*4);
            float4 b4 = *(const float4*)(Bs + k*64 + tx*4);
            acc[0][0] += a4.x*b4.x; acc[0][1] += a4.x*b4.y; acc[0][2] += a4.x*b4.z; acc[0][3] += a4.x*b4.w;
            acc[1][0] += a4.y*b4.x; acc[1][1] += a4.y*b4.y; acc[1][2] += a4.y*b4.z; acc[1][3] += a4.y*b4.w;
            acc[2][0] += a4.z*b4.x; acc[2][1] += a4.z*b4.y; acc[2][2] += a4.z*b4.z; acc[2][3] += a4.z*b4.w;
            acc[3][0] += a4.w*b4.x; acc[3][1] += a4.w*b4.y; acc[3][2] += a4.w*b4.z; acc[3][3] += a4.w*b4.w;
        }
        #pragma unroll
        for (int i = 0; i < 4; i++) {
            const int r = m0 + ty*4 + i;
            const int h = r & 15, t = (r >> 4) & 1023, b = r >> 14;
            float* dst = Os[w] + (((size_t)(b*NH + h))*NT + t)*NS + tx*4;
            *(float4*)dst = make_float4(acc[i][0], acc[i][1], acc[i][2], acc[i][3]);
        }
    }
}

// ---------------------------------------------------------------------------
// K2: per-(b,h) mean of V over all t (padded rows: softmax exactly uniform)
// ---------------------------------------------------------------------------
__global__ __launch_bounds__(64) void vmean_kernel()
{
    const int bh = blockIdx.x;
    const int o  = threadIdx.x;
    const float* vp = g_V + (size_t)bh * NT * NS + o;
    float sum = 0.f;
    for (int t = 0; t < NT; t++) sum += vp[(size_t)t * NS];
    g_vmean[bh * NS + o] = sum * (1.0f / 1024.0f);
}

// ---------------------------------------------------------------------------
// K3: QEr[b,h,tq,l] = Q[b,h,tq,:] . Er[h,l,:]  (band l >= 1023-tq only)
// ---------------------------------------------------------------------------
__global__ __launch_bounds__(256) void qer_kernel(const float* __restrict__ Er)
{
    const int n0 = blockIdx.x * 64;
    const int m0 = blockIdx.y * 64;
    if (m0 + n0 < 897) return;            // never-read band: skip
    const int bh = blockIdx.z;
    const int h  = bh & 15;
    __shared__ float As[4096];            // transposed Q: As[k*64+m]
    __shared__ float Bs[4096];            // transposed Er: Bs[k*64+n]
    const int tid = threadIdx.x;
    const int tx = tid & 15, ty = tid >> 4;
    const int mr = tid >> 2, k0 = (tid & 3) * 16;

    {
        const float* qp = g_Q + ((size_t)bh*NT + m0 + mr)*NS + k0;
        #pragma unroll
        for (int u = 0; u < 4; u++) {
            float4 v = *(const float4*)(qp + u*4);
            As[(k0+u*4+0)*64 + mr] = v.x;
            As[(k0+u*4+1)*64 + mr] = v.y;
            As[(k0+u*4+2)*64 + mr] = v.z;
            As[(k0+u*4+3)*64 + mr] = v.w;
        }
    }
    {
        const float* ep = Er + ((size_t)h*NT + n0 + mr)*NS + k0;
        #pragma unroll
        for (int u = 0; u < 4; u++) {
            float4 v = *(const float4*)(ep + u*4);
            Bs[(k0+u*4+0)*64 + mr] = v.x;
            Bs[(k0+u*4+1)*64 + mr] = v.y;
            Bs[(k0+u*4+2)*64 + mr] = v.z;
            Bs[(k0+u*4+3)*64 + mr] = v.w;
        }
    }
    __syncthreads();
    float acc[4][4] = {};
    #pragma unroll 8
    for (int k = 0; k < 64; k++) {
        float4 a4 = *(const float4*)(As + k*64 + ty*4);
        float4 b4 = *(const float4*)(Bs + k*64 + tx*4);
        acc[0][0] += a4.x*b4.x; acc[0][1] += a4.x*b4.y; acc[0][2] += a4.x*b4.z; acc[0][3] += a4.x*b4.w;
        acc[1][0] += a4.y*b4.x; acc[1][1] += a4.y*b4.y; acc[1][2] += a4.y*b4.z; acc[1][3] += a4.y*b4.w;
        acc[2][0] += a4.z*b4.x; acc[2][1] += a4.z*b4.y; acc[2][2] += a4.z*b4.z; acc[2][3] += a4.z*b4.w;
        acc[3][0] += a4.w*b4.x; acc[3][1] += a4.w*b4.y; acc[3][2] += a4.w*b4.z; acc[3][3] += a4.w*b4.w;
    }
    #pragma unroll
    for (int i = 0; i < 4; i++) {
        const int tq = m0 + ty*4 + i;
        *(float4*)(g_QEr + ((size_t)bh*NT + tq)*NT + n0 + tx*4) =
            make_float4(acc[i][0], acc[i][1], acc[i][2], acc[i][3]);
    }
}

// ---------------------------------------------------------------------------
// K4: flash-style causal attention + relative bias + online softmax.
// Qs transposed+pre-scaled; K transposed; V row-major (shared buffer);
// P row-major, read as float4 in PV.  Epilogue: reference's scrambled layout.
// ---------------------------------------------------------------------------
__global__ __launch_bounds__(256) void attn_kernel(const int* __restrict__ mask)
{
    const int bh = blockIdx.y;
    const int m0 = blockIdx.x * 64;
    const int b = bh >> 4, h = bh & 15;
    __shared__ float Qs[4096];    // transposed, scaled: Qs[k*64+r]
    __shared__ float KVs[4096];   // K^T [k*64+c] during qk, V [c*64+j] during pv
    __shared__ float Ps[4096];    // row-major
    const int tid = threadIdx.x;
    const int tx = tid & 15, ty = tid >> 4;
    const int mr = tid >> 2, k0 = (tid & 3) * 16;

    {   // Q tile -> transposed + scaled by 1/32
        const float* qp = g_Q + ((size_t)bh*NT + m0 + mr)*NS + k0;
        const float inv = 0.03125f;
        #pragma unroll
        for (int u = 0; u < 4; u++) {
            float4 v = *(const float4*)(qp + u*4);
            Qs[(k0+u*4+0)*64 + mr] = v.x * inv;
            Qs[(k0+u*4+1)*64 + mr] = v.y * inv;
            Qs[(k0+u*4+2)*64 + mr] = v.z * inv;
            Qs[(k0+u*4+3)*64 + mr] = v.w * inv;
        }
    }

    float mrow[4], lrow[4], O[4][4];
    #pragma unroll
    for (int i = 0; i < 4; i++) {
        mrow[i] = -1e30f; lrow[i] = 0.f;
        #pragma unroll
        for (int j = 0; j < 4; j++) O[i][j] = 0.f;
    }

    for (int kt = 0; kt <= (int)blockIdx.x; kt++) {
        const int n0 = kt * 64;
        float4 kreg[4];
        {   // prefetch K tile
            const float* kp = g_K + ((size_t)bh*NT + n0 + mr)*NS + k0;
            #pragma unroll
            for (int u = 0; u < 4; u++) kreg[u] = *(const float4*)(kp + u*4);
        }
        __syncthreads();                       // prior pv reads of KVs done; Qs ready
        #pragma unroll
        for (int u = 0; u < 4; u++) {          // K -> KVs transposed
            KVs[(k0+u*4+0)*64 + mr] = kreg[u].x;
            KVs[(k0+u*4+1)*64 + mr] = kreg[u].y;
            KVs[(k0+u*4+2)*64 + mr] = kreg[u].z;
            KVs[(k0+u*4+3)*64 + mr] = kreg[u].w;
        }
        __syncthreads();

        float4 vreg[4];
        {   // prefetch V tile (in flight during qk compute)
            const float4* vs = (const float4*)(g_V + ((size_t)bh*NT + n0)*NS);
            #pragma unroll
            for (int i = 0; i < 4; i++) vreg[i] = vs[tid + i*256];
        }

        float s[4][4] = {};
        #pragma unroll 8
        for (int k = 0; k < 64; k++) {
            float4 a4 = *(const float4*)(Qs + k*64 + ty*4);
            float4 b4 = *(const float4*)(KVs + k*64 + tx*4);
            s[0][0] += a4.x*b4.x; s[0][1] += a4.x*b4.y; s[0][2] += a4.x*b4.z; s[0][3] += a4.x*b4.w;
            s[1][0] += a4.y*b4.x; s[1][1] += a4.y*b4.y; s[1][2] += a4.y*b4.z; s[1][3] += a4.y*b4.w;
            s[2][0] += a4.z*b4.x; s[2][1] += a4.z*b4.y; s[2][2] += a4.z*b4.z; s[2][3] += a4.z*b4.w;
            s[3][0] += a4.w*b4.x; s[3][1] += a4.w*b4.y; s[3][2] += a4.w*b4.z; s[3][3] += a4.w*b4.w;
        }

        #pragma unroll
        for (int i = 0; i < 4; i++) {
            const int tq = m0 + ty*4 + i;
            const float* qer_row = g_QEr + ((size_t)bh*NT + tq)*NT + (1023 - tq);
            #pragma unroll
            for (int j = 0; j < 4; j++) {
                const int tk = n0 + tx*4 + j;
                if (tk > tq) s[i][j] = NEGV;
                else         s[i][j] += qer_row[tk];
            }
        }

        #pragma unroll
        for (int i = 0; i < 4; i++) {
            float rm = fmaxf(fmaxf(s[i][0], s[i][1]), fmaxf(s[i][2], s[i][3]));
            #pragma unroll
            for (int o = 8; o >= 1; o >>= 1)
                rm = fmaxf(rm, __shfl_xor_sync(0xffffffffu, rm, o, 16));
            const float mn = fmaxf(mrow[i], rm);
            const float alpha = __expf(mrow[i] - mn);
            mrow[i] = mn;
            float rs = 0.f;
            #pragma unroll
            for (int j = 0; j < 4; j++) {
                s[i][j] = __expf(s[i][j] - mn);
                rs += s[i][j];
            }
            #pragma unroll
            for (int o = 8; o >= 1; o >>= 1)
                rs += __shfl_xor_sync(0xffffffffu, rs, o, 16);
            lrow[i] = lrow[i]*alpha + rs;
            #pragma unroll
            for (int j = 0; j < 4; j++) O[i][j] *= alpha;
            *(float4*)(Ps + (ty*4+i)*64 + tx*4) =
                make_float4(s[i][0], s[i][1], s[i][2], s[i][3]);
        }
        __syncthreads();                       // Ps visible; KVs(K) reads done
        {   // V tile -> KVs row-major
            float4* dst = (float4*)KVs;
            #pragma unroll
            for (int i = 0; i < 4; i++) dst[tid + i*256] = vreg[i];
        }
        __syncthreads();

        #pragma unroll 4
        for (int c4 = 0; c4 < 16; c4++) {
            float p[4][4];
            #pragma unroll
            for (int i = 0; i < 4; i++)
                *(float4*)p[i] = *(const float4*)(Ps + (ty*4+i)*64 + c4*4);
            #pragma unroll
            for (int cc = 0; cc < 4; cc++) {
                float4 v4 = *(const float4*)(KVs + (c4*4+cc)*64 + tx*4);
                #pragma unroll
                for (int i = 0; i < 4; i++) {
                    O[i][0] += p[i][cc]*v4.x; O[i][1] += p[i][cc]*v4.y;
                    O[i][2] += p[i][cc]*v4.z; O[i][3] += p[i][cc]*v4.w;
                }
            }
        }
    }

    #pragma unroll
    for (int i = 0; i < 4; i++) {
        const int tq = m0 + ty*4 + i;
        float4 o4;
        if (mask[b*NT + tq] == 0) {            // padded row: exact uniform softmax
            const float* vm = g_vmean + bh*NS + tx*4;
            o4 = make_float4(vm[0], vm[1], vm[2], vm[3]);
        } else {
            const float invl = 1.0f / lrow[i];
            o4 = make_float4(O[i][0]*invl, O[i][1]*invl, O[i][2]*invl, O[i][3]*invl);
        }
        // Reference layout: (b,h,t,s) flattened as (b, h*64+t/16, (t%16)*64+s)
        const int rnew = h * 64 + (tq >> 4);
        const int cnew = (tq & 15) * 64 + tx * 4;
        *(float4*)(g_attn + ((size_t)(b*NT + rnew))*NE + cnew) = o4;
    }
}

// ---------------------------------------------------------------------------
// K5: out = attn @ Wo^T + bo   (M=4096, N=1024, K=1024)
// ---------------------------------------------------------------------------
__global__ __launch_bounds__(256) void out_kernel(
    const float* __restrict__ Wo, const float* __restrict__ bo,
    float* __restrict__ out)
{
    const int n0 = blockIdx.x * 64;
    const int m0 = blockIdx.y * 64;
    __shared__ float As[4096];   // transposed: As[k*64+m]
    __shared__ float Bs[4096];   // transposed: Bs[k*64+n]
    const int tid = threadIdx.x;
    const int tx = tid & 15, ty = tid >> 4;
    const int mr = tid >> 2, k0 = (tid & 3) * 16;
    float acc[4][4] = {};

    for (int kc = 0; kc < 16; kc++) {
        float4 areg[4], breg[4];
        {
            const float* ap = g_attn + (size_t)(m0 + mr)*NE + kc*64 + k0;
            const float* wp = Wo + (size_t)(n0 + mr)*NE + kc*64 + k0;
            #pragma unroll
            for (int u = 0; u < 4; u++) {
                areg[u] = *(const float4*)(ap + u*4);
                breg[u] = *(const float4*)(wp + u*4);
            }
        }
        __syncthreads();
        #pragma unroll
        for (int u = 0; u < 4; u++) {
            As[(k0+u*4+0)*64 + mr] = areg[u].x;
            As[(k0+u*4+1)*64 + mr] = areg[u].y;
            As[(k0+u*4+2)*64 + mr] = areg[u].z;
            As[(k0+u*4+3)*64 + mr] = areg[u].w;
            Bs[(k0+u*4+0)*64 + mr] = breg[u].x;
            Bs[(k0+u*4+1)*64 + mr] = breg[u].y;
            Bs[(k0+u*4+2)*64 + mr] = breg[u].z;
            Bs[(k0+u*4+3)*64 + mr] = breg[u].w;
        }
        __syncthreads();
        #pragma unroll 8
        for (int k = 0; k < 64; k++) {
            float4 a4 = *(const float4*)(As + k*64 + ty*4);
            float4 b4 = *(const float4*)(Bs + k*64 + tx*4);
            acc[0][0] += a4.x*b4.x; acc[0][1] += a4.x*b4.y; acc[0][2] += a4.x*b4.z; acc[0][3] += a4.x*b4.w;
            acc[1][0] += a4.y*b4.x; acc[1][1] += a4.y*b4.y; acc[1][2] += a4.y*b4.z; acc[1][3] += a4.y*b4.w;
            acc[2][0] += a4.z*b4.x; acc[2][1] += a4.z*b4.y; acc[2][2] += a4.z*b4.z; acc[2][3] += a4.z*b4.w;
            acc[3][0] += a4.w*b4.x; acc[3][1] += a4.w*b4.y; acc[3][2] += a4.w*b4.z; acc[3][3] += a4.w*b4.w;
        }
    }
    float4 bb = *(const float4*)(bo + n0 + tx*4);
    #pragma unroll
    for (int i = 0; i < 4; i++) {
        float* dst = out + (size_t)(m0 + ty*4 + i)*NE + n0 + tx*4;
        *(float4*)dst = make_float4(acc[i][0]+bb.x, acc[i][1]+bb.y,
                                    acc[i][2]+bb.z, acc[i][3]+bb.w);
    }
}

// ---------------------------------------------------------------------------
extern "C" void kernel_launch(void* const* d_in, const int* in_sizes, int n_in,
                              void* d_out, int out_size)
{
    const float* x    = (const float*)d_in[0];
    const int*   mask = (const int*)  d_in[1];
    const float* Wq   = (const float*)d_in[2];
    const float* Wk   = (const float*)d_in[3];
    const float* Wv   = (const float*)d_in[4];
    const float* Er   = (const float*)d_in[5];
    const float* Wo   = (const float*)d_in[6];
    const float* bo   = (const float*)d_in[7];
    float* out = (float*)d_out;

    proj_kernel<<<1024, 256>>>(x, Wq, Wk, Wv);
    vmean_kernel<<<64, 64>>>();
    qer_kernel<<<dim3(16, 16, 64), 256>>>(Er);
    attn_kernel<<<dim3(16, 64), 256>>>(mask);
    out_kernel<<<dim3(16, 64), 256>>>(Wo, bo, out);
}

// round 13
// speedup vs baseline: 1.8905x; 1.4421x over previous
#include <cuda_runtime.h>

#define NB 4
#define NT 1024
#define NH 16
#define NS 64
#define NE 1024
#define NEGV -1000000000.0f

// Scratch (device globals — allocation-free kernel_launch)
static __device__ float g_Q[NB*NH*NT*NS];
static __device__ float g_K[NB*NH*NT*NS];
static __device__ float g_V[NB*NH*NT*NS];
static __device__ float g_QEr[(size_t)NB*NH*NT*NT];   // only upper band used
static __device__ float g_attn[NB*NT*NE];             // reference's scrambled layout
static __device__ float g_vmean[NB*NH*NS];

// ---------------------------------------------------------------------------
// tf32 helpers (mma.sync m16n8k8 fallback-HMMA path on sm_103a)
// ---------------------------------------------------------------------------
__device__ __forceinline__ unsigned tf32u(float x) {
    unsigned u;
    asm("cvt.rna.tf32.f32 %0, %1;" : "=r"(u) : "f"(x));
    return u;
}

#define MMA_TF32(d, a, b)                                                     \
    asm volatile(                                                             \
        "mma.sync.aligned.m16n8k8.row.col.f32.tf32.tf32.f32 "                 \
        "{%0,%1,%2,%3}, {%4,%5,%6,%7}, {%8,%9}, {%0,%1,%2,%3};"               \
        : "+f"((d)[0]), "+f"((d)[1]), "+f"((d)[2]), "+f"((d)[3])              \
        : "r"((a)[0]), "r"((a)[1]), "r"((a)[2]), "r"((a)[3]),                 \
          "r"((b)[0]), "r"((b)[1]))

// ---------------------------------------------------------------------------
// K1: QKV projection (fp32; small).  x viewed as [65536,64].
// ---------------------------------------------------------------------------
__global__ __launch_bounds__(256) void proj_kernel(
    const float* __restrict__ x, const float* __restrict__ Wq,
    const float* __restrict__ Wk, const float* __restrict__ Wv)
{
    __shared__ float As[4096];   // transposed: As[k*64+m]
    __shared__ float Bs[4096];   // transposed: Bs[k*64+o]
    const int tid = threadIdx.x;
    const int tx = tid & 15, ty = tid >> 4;
    const int m0 = blockIdx.x * 64;
    const int mr = tid >> 2, k0 = (tid & 3) * 16;

    {   // x tile -> As transposed
        const float* xp = x + (size_t)(m0 + mr) * 64 + k0;
        #pragma unroll
        for (int u = 0; u < 4; u++) {
            float4 v = *(const float4*)(xp + u*4);
            As[(k0+u*4+0)*64 + mr] = v.x;
            As[(k0+u*4+1)*64 + mr] = v.y;
            As[(k0+u*4+2)*64 + mr] = v.z;
            As[(k0+u*4+3)*64 + mr] = v.w;
        }
    }

    const float* Ws[3] = {Wq, Wk, Wv};
    float* Os[3] = {g_Q, g_K, g_V};

    for (int w = 0; w < 3; w++) {
        float4 breg[4];
        {
            const float* wp = Ws[w] + mr * 64 + k0;
            #pragma unroll
            for (int u = 0; u < 4; u++) breg[u] = *(const float4*)(wp + u*4);
        }
        __syncthreads();
        #pragma unroll
        for (int u = 0; u < 4; u++) {
            Bs[(k0+u*4+0)*64 + mr] = breg[u].x;
            Bs[(k0+u*4+1)*64 + mr] = breg[u].y;
            Bs[(k0+u*4+2)*64 + mr] = breg[u].z;
            Bs[(k0+u*4+3)*64 + mr] = breg[u].w;
        }
        __syncthreads();
        float acc[4][4] = {};
        #pragma unroll 8
        for (int k = 0; k < 64; k++) {
            float4 a4 = *(const float4*)(As + k*64 + ty*4);
            float4 b4 = *(const float4*)(Bs + k*64 + tx*4);
            acc[0][0] += a4.x*b4.x; acc[0][1] += a4.x*b4.y; acc[0][2] += a4.x*b4.z; acc[0][3] += a4.x*b4.w;
            acc[1][0] += a4.y*b4.x; acc[1][1] += a4.y*b4.y; acc[1][2] += a4.y*b4.z; acc[1][3] += a4.y*b4.w;
            acc[2][0] += a4.z*b4.x; acc[2][1] += a4.z*b4.y; acc[2][2] += a4.z*b4.z; acc[2][3] += a4.z*b4.w;
            acc[3][0] += a4.w*b4.x; acc[3][1] += a4.w*b4.y; acc[3][2] += a4.w*b4.z; acc[3][3] += a4.w*b4.w;
        }
        #pragma unroll
        for (int i = 0; i < 4; i++) {
            const int r = m0 + ty*4 + i;
            const int h = r & 15, t = (r >> 4) & 1023, b = r >> 14;
            float* dst = Os[w] + (((size_t)(b*NH + h))*NT + t)*NS + tx*4;
            *(float4*)dst = make_float4(acc[i][0], acc[i][1], acc[i][2], acc[i][3]);
        }
    }
}

// ---------------------------------------------------------------------------
// K2: per-(b,h) mean of V over all t (padded rows: softmax exactly uniform)
// ---------------------------------------------------------------------------
__global__ __launch_bounds__(64) void vmean_kernel()
{
    const int bh = blockIdx.x;
    const int o  = threadIdx.x;
    const float* vp = g_V + (size_t)bh * NT * NS + o;
    float sum = 0.f;
    for (int t = 0; t < NT; t++) sum += vp[(size_t)t * NS];
    g_vmean[bh * NS + o] = sum * (1.0f / 1024.0f);
}

// ---------------------------------------------------------------------------
// K3 (tf32 tensor): QEr[b,h,tq,l] = Q[b,h,tq,:].Er[h,l,:], band only.
// Block tile 128(M) x 64(N), K=64 single chunk. 8 warps, 32x32 per warp.
// smem XOR-swizzled: word = row*64 + (k ^ ((row&7)<<2)); conflict-free frags.
// ---------------------------------------------------------------------------
__global__ __launch_bounds__(256) void qer_tf32_kernel(const float* __restrict__ Er)
{
    const int n0 = blockIdx.x * 64;
    const int m0 = blockIdx.y * 128;
    if (m0 + n0 < 833) return;            // tile never gathered (l >= 1023-tq)
    const int bh = blockIdx.z;
    const int h  = bh & 15;

    __shared__ unsigned As[8192];   // 128 x 64 tf32
    __shared__ unsigned Bs[4096];   // 64 x 64 tf32
    const int tid = threadIdx.x;
    const int lane = tid & 31, wid = tid >> 5;
    const int mw = wid & 3, nw = wid >> 2;         // 4 warps in M, 2 in N
    const int r4 = lane >> 2, c4 = lane & 3;
    const int swz = r4 << 2;

    {   // A: Q rows m0..m0+127
        #pragma unroll
        for (int i = 0; i < 8; i++) {
            const int idx = tid + i*256, row = idx >> 4, cb = (idx & 15) * 4;
            float4 v = *(const float4*)(g_Q + ((size_t)bh*NT + m0 + row)*NS + cb);
            *(uint4*)&As[row*64 + (cb ^ ((row & 7) << 2))] =
                make_uint4(tf32u(v.x), tf32u(v.y), tf32u(v.z), tf32u(v.w));
        }
    }
    {   // B: Er rows n0..n0+63
        #pragma unroll
        for (int i = 0; i < 4; i++) {
            const int idx = tid + i*256, row = idx >> 4, cb = (idx & 15) * 4;
            float4 v = *(const float4*)(Er + ((size_t)h*NT + n0 + row)*NS + cb);
            *(uint4*)&Bs[row*64 + (cb ^ ((row & 7) << 2))] =
                make_uint4(tf32u(v.x), tf32u(v.y), tf32u(v.z), tf32u(v.w));
        }
    }
    __syncthreads();

    float acc[2][4][4] = {};
    #pragma unroll
    for (int ks = 0; ks < 8; ks++) {
        const int k0 = ks * 8;
        unsigned a[2][4], b[4][2];
        #pragma unroll
        for (int mt = 0; mt < 2; mt++) {
            const int base = (mw*32 + mt*16 + r4) * 64;
            a[mt][0] = As[base       + ((k0 + c4)     ^ swz)];
            a[mt][1] = As[base + 512 + ((k0 + c4)     ^ swz)];
            a[mt][2] = As[base       + ((k0 + c4 + 4) ^ swz)];
            a[mt][3] = As[base + 512 + ((k0 + c4 + 4) ^ swz)];
        }
        #pragma unroll
        for (int nt = 0; nt < 4; nt++) {
            const int base = (nw*32 + nt*8 + r4) * 64;
            b[nt][0] = Bs[base + ((k0 + c4)     ^ swz)];
            b[nt][1] = Bs[base + ((k0 + c4 + 4) ^ swz)];
        }
        #pragma unroll
        for (int mt = 0; mt < 2; mt++)
            #pragma unroll
            for (int nt = 0; nt < 4; nt++)
                MMA_TF32(acc[mt][nt], a[mt], b[nt]);
    }

    #pragma unroll
    for (int mt = 0; mt < 2; mt++) {
        const int ro = m0 + mw*32 + mt*16 + r4;
        #pragma unroll
        for (int nt = 0; nt < 4; nt++) {
            const int co = n0 + nw*32 + nt*8 + c4*2;
            float* p0 = g_QEr + ((size_t)bh*NT + ro)*NT + co;
            *(float2*)p0 = make_float2(acc[mt][nt][0], acc[mt][nt][1]);
            float* p1 = g_QEr + ((size_t)bh*NT + ro + 8)*NT + co;
            *(float2*)p1 = make_float2(acc[mt][nt][2], acc[mt][nt][3]);
        }
    }
}

// ---------------------------------------------------------------------------
// K4: flash-style causal attention (fp32, unchanged from R10-pass version)
// ---------------------------------------------------------------------------
__global__ __launch_bounds__(256) void attn_kernel(const int* __restrict__ mask)
{
    const int bh = blockIdx.y;
    const int m0 = blockIdx.x * 64;
    const int b = bh >> 4, h = bh & 15;
    __shared__ float Qs[4096];    // transposed, scaled: Qs[k*64+r]
    __shared__ float KVs[4096];   // K^T [k*64+c] during qk, V [c*64+j] during pv
    __shared__ float Ps[4096];    // row-major
    const int tid = threadIdx.x;
    const int tx = tid & 15, ty = tid >> 4;
    const int mr = tid >> 2, k0 = (tid & 3) * 16;

    {   // Q tile -> transposed + scaled by 1/32
        const float* qp = g_Q + ((size_t)bh*NT + m0 + mr)*NS + k0;
        const float inv = 0.03125f;
        #pragma unroll
        for (int u = 0; u < 4; u++) {
            float4 v = *(const float4*)(qp + u*4);
            Qs[(k0+u*4+0)*64 + mr] = v.x * inv;
            Qs[(k0+u*4+1)*64 + mr] = v.y * inv;
            Qs[(k0+u*4+2)*64 + mr] = v.z * inv;
            Qs[(k0+u*4+3)*64 + mr] = v.w * inv;
        }
    }

    float mrow[4], lrow[4], O[4][4];
    #pragma unroll
    for (int i = 0; i < 4; i++) {
        mrow[i] = -1e30f; lrow[i] = 0.f;
        #pragma unroll
        for (int j = 0; j < 4; j++) O[i][j] = 0.f;
    }

    for (int kt = 0; kt <= (int)blockIdx.x; kt++) {
        const int n0 = kt * 64;
        float4 kreg[4];
        {
            const float* kp = g_K + ((size_t)bh*NT + n0 + mr)*NS + k0;
            #pragma unroll
            for (int u = 0; u < 4; u++) kreg[u] = *(const float4*)(kp + u*4);
        }
        __syncthreads();
        #pragma unroll
        for (int u = 0; u < 4; u++) {
            KVs[(k0+u*4+0)*64 + mr] = kreg[u].x;
            KVs[(k0+u*4+1)*64 + mr] = kreg[u].y;
            KVs[(k0+u*4+2)*64 + mr] = kreg[u].z;
            KVs[(k0+u*4+3)*64 + mr] = kreg[u].w;
        }
        __syncthreads();

        float4 vreg[4];
        {
            const float4* vs = (const float4*)(g_V + ((size_t)bh*NT + n0)*NS);
            #pragma unroll
            for (int i = 0; i < 4; i++) vreg[i] = vs[tid + i*256];
        }

        float s[4][4] = {};
        #pragma unroll 8
        for (int k = 0; k < 64; k++) {
            float4 a4 = *(const float4*)(Qs + k*64 + ty*4);
            float4 b4 = *(const float4*)(KVs + k*64 + tx*4);
            s[0][0] += a4.x*b4.x; s[0][1] += a4.x*b4.y; s[0][2] += a4.x*b4.z; s[0][3] += a4.x*b4.w;
            s[1][0] += a4.y*b4.x; s[1][1] += a4.y*b4.y; s[1][2] += a4.y*b4.z; s[1][3] += a4.y*b4.w;
            s[2][0] += a4.z*b4.x; s[2][1] += a4.z*b4.y; s[2][2] += a4.z*b4.z; s[2][3] += a4.z*b4.w;
            s[3][0] += a4.w*b4.x; s[3][1] += a4.w*b4.y; s[3][2] += a4.w*b4.z; s[3][3] += a4.w*b4.w;
        }

        #pragma unroll
        for (int i = 0; i < 4; i++) {
            const int tq = m0 + ty*4 + i;
            const float* qer_row = g_QEr + ((size_t)bh*NT + tq)*NT + (1023 - tq);
            #pragma unroll
            for (int j = 0; j < 4; j++) {
                const int tk = n0 + tx*4 + j;
                if (tk > tq) s[i][j] = NEGV;
                else         s[i][j] += qer_row[tk];
            }
        }

        #pragma unroll
        for (int i = 0; i < 4; i++) {
            float rm = fmaxf(fmaxf(s[i][0], s[i][1]), fmaxf(s[i][2], s[i][3]));
            #pragma unroll
            for (int o = 8; o >= 1; o >>= 1)
                rm = fmaxf(rm, __shfl_xor_sync(0xffffffffu, rm, o, 16));
            const float mn = fmaxf(mrow[i], rm);
            const float alpha = __expf(mrow[i] - mn);
            mrow[i] = mn;
            float rs = 0.f;
            #pragma unroll
            for (int j = 0; j < 4; j++) {
                s[i][j] = __expf(s[i][j] - mn);
                rs += s[i][j];
            }
            #pragma unroll
            for (int o = 8; o >= 1; o >>= 1)
                rs += __shfl_xor_sync(0xffffffffu, rs, o, 16);
            lrow[i] = lrow[i]*alpha + rs;
            #pragma unroll
            for (int j = 0; j < 4; j++) O[i][j] *= alpha;
            *(float4*)(Ps + (ty*4+i)*64 + tx*4) =
                make_float4(s[i][0], s[i][1], s[i][2], s[i][3]);
        }
        __syncthreads();
        {
            float4* dst = (float4*)KVs;
            #pragma unroll
            for (int i = 0; i < 4; i++) dst[tid + i*256] = vreg[i];
        }
        __syncthreads();

        #pragma unroll 4
        for (int c4i = 0; c4i < 16; c4i++) {
            float p[4][4];
            #pragma unroll
            for (int i = 0; i < 4; i++)
                *(float4*)p[i] = *(const float4*)(Ps + (ty*4+i)*64 + c4i*4);
            #pragma unroll
            for (int cc = 0; cc < 4; cc++) {
                float4 v4 = *(const float4*)(KVs + (c4i*4+cc)*64 + tx*4);
                #pragma unroll
                for (int i = 0; i < 4; i++) {
                    O[i][0] += p[i][cc]*v4.x; O[i][1] += p[i][cc]*v4.y;
                    O[i][2] += p[i][cc]*v4.z; O[i][3] += p[i][cc]*v4.w;
                }
            }
        }
    }

    #pragma unroll
    for (int i = 0; i < 4; i++) {
        const int tq = m0 + ty*4 + i;
        float4 o4;
        if (mask[b*NT + tq] == 0) {
            const float* vm = g_vmean + bh*NS + tx*4;
            o4 = make_float4(vm[0], vm[1], vm[2], vm[3]);
        } else {
            const float invl = 1.0f / lrow[i];
            o4 = make_float4(O[i][0]*invl, O[i][1]*invl, O[i][2]*invl, O[i][3]*invl);
        }
        // Reference layout: (b,h,t,s) flattened as (b, h*64+t/16, (t%16)*64+s)
        const int rnew = h * 64 + (tq >> 4);
        const int cnew = (tq & 15) * 64 + tx * 4;
        *(float4*)(g_attn + ((size_t)(b*NT + rnew))*NE + cnew) = o4;
    }
}

// ---------------------------------------------------------------------------
// K5 (tf32 tensor): out = attn @ Wo^T + bo.  M=4096, N=1024, K=1024.
// Block tile 128(M) x 64(N), 16 K-chunks of 64.  Same swizzle as qer.
// ---------------------------------------------------------------------------
__global__ __launch_bounds__(256) void out_tf32_kernel(
    const float* __restrict__ Wo, const float* __restrict__ bo,
    float* __restrict__ out)
{
    const int n0 = blockIdx.x * 64;
    const int m0 = blockIdx.y * 128;
    __shared__ unsigned As[8192];   // 128 x 64 tf32
    __shared__ unsigned Bs[4096];   // 64 x 64 tf32
    const int tid = threadIdx.x;
    const int lane = tid & 31, wid = tid >> 5;
    const int mw = wid & 3, nw = wid >> 2;
    const int r4 = lane >> 2, c4 = lane & 3;
    const int swz = r4 << 2;

    float acc[2][4][4] = {};

    for (int kc = 0; kc < 16; kc++) {
        __syncthreads();
        {   // A: attn rows m0..m0+127, cols kc*64..
            #pragma unroll
            for (int i = 0; i < 8; i++) {
                const int idx = tid + i*256, row = idx >> 4, cb = (idx & 15) * 4;
                float4 v = *(const float4*)(g_attn + (size_t)(m0 + row)*NE + kc*64 + cb);
                *(uint4*)&As[row*64 + (cb ^ ((row & 7) << 2))] =
                    make_uint4(tf32u(v.x), tf32u(v.y), tf32u(v.z), tf32u(v.w));
            }
        }
        {   // B: Wo rows n0..n0+63, cols kc*64..
            #pragma unroll
            for (int i = 0; i < 4; i++) {
                const int idx = tid + i*256, row = idx >> 4, cb = (idx & 15) * 4;
                float4 v = *(const float4*)(Wo + (size_t)(n0 + row)*NE + kc*64 + cb);
                *(uint4*)&Bs[row*64 + (cb ^ ((row & 7) << 2))] =
                    make_uint4(tf32u(v.x), tf32u(v.y), tf32u(v.z), tf32u(v.w));
            }
        }
        __syncthreads();

        #pragma unroll
        for (int ks = 0; ks < 8; ks++) {
            const int k0 = ks * 8;
            unsigned a[2][4], b[4][2];
            #pragma unroll
            for (int mt = 0; mt < 2; mt++) {
                const int base = (mw*32 + mt*16 + r4) * 64;
                a[mt][0] = As[base       + ((k0 + c4)     ^ swz)];
                a[mt][1] = As[base + 512 + ((k0 + c4)     ^ swz)];
                a[mt][2] = As[base       + ((k0 + c4 + 4) ^ swz)];
                a[mt][3] = As[base + 512 + ((k0 + c4 + 4) ^ swz)];
            }
            #pragma unroll
            for (int nt = 0; nt < 4; nt++) {
                const int base = (nw*32 + nt*8 + r4) * 64;
                b[nt][0] = Bs[base + ((k0 + c4)     ^ swz)];
                b[nt][1] = Bs[base + ((k0 + c4 + 4) ^ swz)];
            }
            #pragma unroll
            for (int mt = 0; mt < 2; mt++)
                #pragma unroll
                for (int nt = 0; nt < 4; nt++)
                    MMA_TF32(acc[mt][nt], a[mt], b[nt]);
        }
    }

    #pragma unroll
    for (int mt = 0; mt < 2; mt++) {
        const int ro = m0 + mw*32 + mt*16 + r4;
        #pragma unroll
        for (int nt = 0; nt < 4; nt++) {
            const int co = n0 + nw*32 + nt*8 + c4*2;
            const float b0 = __ldg(bo + co), b1 = __ldg(bo + co + 1);
            *(float2*)(out + (size_t)ro*NE + co) =
                make_float2(acc[mt][nt][0] + b0, acc[mt][nt][1] + b1);
            *(float2*)(out + (size_t)(ro + 8)*NE + co) =
                make_float2(acc[mt][nt][2] + b0, acc[mt][nt][3] + b1);
        }
    }
}

// ---------------------------------------------------------------------------
extern "C" void kernel_launch(void* const* d_in, const int* in_sizes, int n_in,
                              void* d_out, int out_size)
{
    const float* x    = (const float*)d_in[0];
    const int*   mask = (const int*)  d_in[1];
    const float* Wq   = (const float*)d_in[2];
    const float* Wk   = (const float*)d_in[3];
    const float* Wv   = (const float*)d_in[4];
    const float* Er   = (const float*)d_in[5];
    const float* Wo   = (const float*)d_in[6];
    const float* bo   = (const float*)d_in[7];
    float* out = (float*)d_out;

    proj_kernel<<<1024, 256>>>(x, Wq, Wk, Wv);
    vmean_kernel<<<64, 64>>>();
    qer_tf32_kernel<<<dim3(16, 8, 64), 256>>>(Er);
    attn_kernel<<<dim3(16, 64), 256>>>(mask);
    out_tf32_kernel<<<dim3(16, 32), 256>>>(Wo, bo, out);
}

// round 15
// speedup vs baseline: 2.8882x; 1.5277x over previous
#include <cuda_runtime.h>

#define NB 4
#define NT 1024
#define NH 16
#define NS 64
#define NE 1024
#define NEGV -1000000000.0f

// Scratch (device globals — allocation-free kernel_launch)
static __device__ float g_Q[NB*NH*NT*NS];
static __device__ float g_K[NB*NH*NT*NS];
static __device__ float g_V[NB*NH*NT*NS];
static __device__ float g_QEr[(size_t)NB*NH*NT*NT];   // only upper band used
static __device__ float g_attn[NB*NT*NE];             // reference's scrambled layout
static __device__ float g_vmean[NB*NH*NS];

// ---------------------------------------------------------------------------
// tf32 helpers (m16n8k8 fragment layout validated on HW in qer_tf32, R13)
// ---------------------------------------------------------------------------
__device__ __forceinline__ unsigned tf32u(float x) {
    unsigned u;
    asm("cvt.rna.tf32.f32 %0, %1;" : "=r"(u) : "f"(x));
    return u;
}

#define MMA_TF32(d, a, b)                                                     \
    asm volatile(                                                             \
        "mma.sync.aligned.m16n8k8.row.col.f32.tf32.tf32.f32 "                 \
        "{%0,%1,%2,%3}, {%4,%5,%6,%7}, {%8,%9}, {%0,%1,%2,%3};"               \
        : "+f"((d)[0]), "+f"((d)[1]), "+f"((d)[2]), "+f"((d)[3])              \
        : "r"((a)[0]), "r"((a)[1]), "r"((a)[2]), "r"((a)[3]),                 \
          "r"((b)[0]), "r"((b)[1]))

// ---------------------------------------------------------------------------
// K1: QKV projection (fp32).  x viewed as [65536,64].
// ---------------------------------------------------------------------------
__global__ __launch_bounds__(256) void proj_kernel(
    const float* __restrict__ x, const float* __restrict__ Wq,
    const float* __restrict__ Wk, const float* __restrict__ Wv)
{
    __shared__ float As[4096];   // transposed: As[k*64+m]
    __shared__ float Bs[4096];   // transposed: Bs[k*64+o]
    const int tid = threadIdx.x;
    const int tx = tid & 15, ty = tid >> 4;
    const int m0 = blockIdx.x * 64;
    const int mr = tid >> 2, k0 = (tid & 3) * 16;

    {   // x tile -> As transposed
        const float* xp = x + (size_t)(m0 + mr) * 64 + k0;
        #pragma unroll
        for (int u = 0; u < 4; u++) {
            float4 v = *(const float4*)(xp + u*4);
            As[(k0+u*4+0)*64 + mr] = v.x;
            As[(k0+u*4+1)*64 + mr] = v.y;
            As[(k0+u*4+2)*64 + mr] = v.z;
            As[(k0+u*4+3)*64 + mr] = v.w;
        }
    }

    const float* Ws[3] = {Wq, Wk, Wv};
    float* Os[3] = {g_Q, g_K, g_V};

    for (int w = 0; w < 3; w++) {
        float4 breg[4];
        {
            const float* wp = Ws[w] + mr * 64 + k0;
            #pragma unroll
            for (int u = 0; u < 4; u++) breg[u] = *(const float4*)(wp + u*4);
        }
        __syncthreads();
        #pragma unroll
        for (int u = 0; u < 4; u++) {
            Bs[(k0+u*4+0)*64 + mr] = breg[u].x;
            Bs[(k0+u*4+1)*64 + mr] = breg[u].y;
            Bs[(k0+u*4+2)*64 + mr] = breg[u].z;
            Bs[(k0+u*4+3)*64 + mr] = breg[u].w;
        }
        __syncthreads();
        float acc[4][4] = {};
        #pragma unroll 8
        for (int k = 0; k < 64; k++) {
            float4 a4 = *(const float4*)(As + k*64 + ty*4);
            float4 b4 = *(const float4*)(Bs + k*64 + tx*4);
            acc[0][0] += a4.x*b4.x; acc[0][1] += a4.x*b4.y; acc[0][2] += a4.x*b4.z; acc[0][3] += a4.x*b4.w;
            acc[1][0] += a4.y*b4.x; acc[1][1] += a4.y*b4.y; acc[1][2] += a4.y*b4.z; acc[1][3] += a4.y*b4.w;
            acc[2][0] += a4.z*b4.x; acc[2][1] += a4.z*b4.y; acc[2][2] += a4.z*b4.z; acc[2][3] += a4.z*b4.w;
            acc[3][0] += a4.w*b4.x; acc[3][1] += a4.w*b4.y; acc[3][2] += a4.w*b4.z; acc[3][3] += a4.w*b4.w;
        }
        #pragma unroll
        for (int i = 0; i < 4; i++) {
            const int r = m0 + ty*4 + i;
            const int h = r & 15, t = (r >> 4) & 1023, b = r >> 14;
            float* dst = Os[w] + (((size_t)(b*NH + h))*NT + t)*NS + tx*4;
            *(float4*)dst = make_float4(acc[i][0], acc[i][1], acc[i][2], acc[i][3]);
        }
    }
}

// ---------------------------------------------------------------------------
// K2: per-(b,h) mean of V over all t (padded rows: softmax exactly uniform)
// ---------------------------------------------------------------------------
__global__ __launch_bounds__(64) void vmean_kernel()
{
    const int bh = blockIdx.x;
    const int o  = threadIdx.x;
    const float* vp = g_V + (size_t)bh * NT * NS + o;
    float sum = 0.f;
    for (int t = 0; t < NT; t++) sum += vp[(size_t)t * NS];
    g_vmean[bh * NS + o] = sum * (1.0f / 1024.0f);
}

// ---------------------------------------------------------------------------
// K3 (tf32 tensor): QEr[b,h,tq,l] = Q[b,h,tq,:].Er[h,l,:], band only.
// ---------------------------------------------------------------------------
__global__ __launch_bounds__(256) void qer_tf32_kernel(const float* __restrict__ Er)
{
    const int n0 = blockIdx.x * 64;
    const int m0 = blockIdx.y * 128;
    if (m0 + n0 < 833) return;            // tile never gathered (l >= 1023-tq)
    const int bh = blockIdx.z;
    const int h  = bh & 15;

    __shared__ unsigned As[8192];   // 128 x 64 tf32
    __shared__ unsigned Bs[4096];   // 64 x 64 tf32
    const int tid = threadIdx.x;
    const int lane = tid & 31, wid = tid >> 5;
    const int mw = wid & 3, nw = wid >> 2;         // 4 warps in M, 2 in N
    const int r4 = lane >> 2, c4 = lane & 3;
    const int swz = r4 << 2;

    {
        #pragma unroll
        for (int i = 0; i < 8; i++) {
            const int idx = tid + i*256, row = idx >> 4, cb = (idx & 15) * 4;
            float4 v = *(const float4*)(g_Q + ((size_t)bh*NT + m0 + row)*NS + cb);
            *(uint4*)&As[row*64 + (cb ^ ((row & 7) << 2))] =
                make_uint4(tf32u(v.x), tf32u(v.y), tf32u(v.z), tf32u(v.w));
        }
    }
    {
        #pragma unroll
        for (int i = 0; i < 4; i++) {
            const int idx = tid + i*256, row = idx >> 4, cb = (idx & 15) * 4;
            float4 v = *(const float4*)(Er + ((size_t)h*NT + n0 + row)*NS + cb);
            *(uint4*)&Bs[row*64 + (cb ^ ((row & 7) << 2))] =
                make_uint4(tf32u(v.x), tf32u(v.y), tf32u(v.z), tf32u(v.w));
        }
    }
    __syncthreads();

    float acc[2][4][4] = {};
    #pragma unroll
    for (int ks = 0; ks < 8; ks++) {
        const int k0 = ks * 8;
        unsigned a[2][4], b[4][2];
        #pragma unroll
        for (int mt = 0; mt < 2; mt++) {
            const int base = (mw*32 + mt*16 + r4) * 64;
            a[mt][0] = As[base       + ((k0 + c4)     ^ swz)];
            a[mt][1] = As[base + 512 + ((k0 + c4)     ^ swz)];
            a[mt][2] = As[base       + ((k0 + c4 + 4) ^ swz)];
            a[mt][3] = As[base + 512 + ((k0 + c4 + 4) ^ swz)];
        }
        #pragma unroll
        for (int nt = 0; nt < 4; nt++) {
            const int base = (nw*32 + nt*8 + r4) * 64;
            b[nt][0] = Bs[base + ((k0 + c4)     ^ swz)];
            b[nt][1] = Bs[base + ((k0 + c4 + 4) ^ swz)];
        }
        #pragma unroll
        for (int mt = 0; mt < 2; mt++)
            #pragma unroll
            for (int nt = 0; nt < 4; nt++)
                MMA_TF32(acc[mt][nt], a[mt], b[nt]);
    }

    #pragma unroll
    for (int mt = 0; mt < 2; mt++) {
        const int ro = m0 + mw*32 + mt*16 + r4;
        #pragma unroll
        for (int nt = 0; nt < 4; nt++) {
            const int co = n0 + nw*32 + nt*8 + c4*2;
            *(float2*)(g_QEr + ((size_t)bh*NT + ro)*NT + co) =
                make_float2(acc[mt][nt][0], acc[mt][nt][1]);
            *(float2*)(g_QEr + ((size_t)bh*NT + ro + 8)*NT + co) =
                make_float2(acc[mt][nt][2], acc[mt][nt][3]);
        }
    }
}

// ---------------------------------------------------------------------------
// K4 (NEW, tensor-core): flash attention, M=128/block, N=64/ktile, tf32 MMA.
// 8 warps all in M (16 rows each). Q held in regs; smem: [Q->P | K | V].
// ---------------------------------------------------------------------------
__global__ __launch_bounds__(256) void attn_tc_kernel(const int* __restrict__ mask)
{
    extern __shared__ unsigned sm[];
    unsigned* SP = sm;            // 8192 words: Q staging, then P
    unsigned* SK = sm + 8192;     // 4096 words: K tile
    unsigned* SV = sm + 12288;    // 4096 words: V tile

    const int tid = threadIdx.x;
    const int lane = tid & 31, w = tid >> 5;
    const int r4 = lane >> 2, c4 = lane & 3;
    const int bh = blockIdx.y, b = bh >> 4, h = bh & 15;
    const int m0 = blockIdx.x * 128;

    {   // stage Q (scaled by 1/32, tf32, swizzled)
        const float inv = 0.03125f;
        #pragma unroll
        for (int i = 0; i < 8; i++) {
            const int idx = tid + i*256, row = idx >> 4, cb = (idx & 15) * 4;
            float4 v = *(const float4*)(g_Q + ((size_t)bh*NT + m0 + row)*NS + cb);
            *(uint4*)&SP[row*64 + (cb ^ ((row & 7) << 2))] =
                make_uint4(tf32u(v.x*inv), tf32u(v.y*inv), tf32u(v.z*inv), tf32u(v.w*inv));
        }
    }
    __syncthreads();

    unsigned qf[8][4];
    const int lrow = w*16 + r4;                 // local row (0..127), row&7 == r4
    #pragma unroll
    for (int ks = 0; ks < 8; ks++) {
        const int k0 = ks*8;
        qf[ks][0] = SP[lrow*64     + ((k0+c4)   ^ (r4<<2))];
        qf[ks][1] = SP[(lrow+8)*64 + ((k0+c4)   ^ (r4<<2))];
        qf[ks][2] = SP[lrow*64     + ((k0+c4+4) ^ (r4<<2))];
        qf[ks][3] = SP[(lrow+8)*64 + ((k0+c4+4) ^ (r4<<2))];
    }

    const int tq0 = m0 + lrow, tq1 = tq0 + 8;
    const float* qer0 = g_QEr + ((size_t)bh*NT + tq0)*NT + (1023 - tq0);
    const float* qer1 = g_QEr + ((size_t)bh*NT + tq1)*NT + (1023 - tq1);

    float O[8][4] = {};
    float mr[2] = {-1e30f, -1e30f};
    float lsum[2] = {0.f, 0.f};

    const int nkt = 2*blockIdx.x + 2;
    for (int kt = 0; kt < nkt; kt++) {
        const int n0 = kt*64;
        __syncthreads();                      // prev PV reads of SK/SV done
        {   // stage K and V tiles (tf32, swizzled)
            #pragma unroll
            for (int i = 0; i < 4; i++) {
                const int idx = tid + i*256, row = idx >> 4, cb = (idx & 15) * 4;
                const int so = row*64 + (cb ^ ((row & 7) << 2));
                float4 kv = *(const float4*)(g_K + ((size_t)bh*NT + n0 + row)*NS + cb);
                *(uint4*)&SK[so] = make_uint4(tf32u(kv.x), tf32u(kv.y), tf32u(kv.z), tf32u(kv.w));
                float4 vv = *(const float4*)(g_V + ((size_t)bh*NT + n0 + row)*NS + cb);
                *(uint4*)&SV[so] = make_uint4(tf32u(vv.x), tf32u(vv.y), tf32u(vv.z), tf32u(vv.w));
            }
        }
        __syncthreads();

        // ---- S = Q.K^T ----
        float S[8][4] = {};
        #pragma unroll
        for (int ks = 0; ks < 8; ks++) {
            const int k0 = ks*8;
            unsigned bb[8][2];
            #pragma unroll
            for (int nt = 0; nt < 8; nt++) {
                const int base = (nt*8 + r4)*64;
                bb[nt][0] = SK[base + ((k0+c4)   ^ (r4<<2))];
                bb[nt][1] = SK[base + ((k0+c4+4) ^ (r4<<2))];
            }
            #pragma unroll
            for (int nt = 0; nt < 8; nt++) MMA_TF32(S[nt], qf[ks], bb[nt]);
        }

        // ---- bias + causal (accumulator layout) ----
        #pragma unroll
        for (int nt = 0; nt < 8; nt++) {
            const int tk = n0 + nt*8 + c4*2;
            S[nt][0] = (tk   <= tq0) ? S[nt][0] + __ldg(qer0+tk)   : NEGV;
            S[nt][1] = (tk+1 <= tq0) ? S[nt][1] + __ldg(qer0+tk+1) : NEGV;
            S[nt][2] = (tk   <= tq1) ? S[nt][2] + __ldg(qer1+tk)   : NEGV;
            S[nt][3] = (tk+1 <= tq1) ? S[nt][3] + __ldg(qer1+tk+1) : NEGV;
        }

        // ---- online softmax (rows r4 / r4+8); lanes of a row differ in c4 ----
        #pragma unroll
        for (int r = 0; r < 2; r++) {
            float rm = S[0][2*r];
            #pragma unroll
            for (int nt = 0; nt < 8; nt++)
                rm = fmaxf(rm, fmaxf(S[nt][2*r], S[nt][2*r+1]));
            rm = fmaxf(rm, __shfl_xor_sync(0xffffffffu, rm, 1));
            rm = fmaxf(rm, __shfl_xor_sync(0xffffffffu, rm, 2));
            const float mn = fmaxf(mr[r], rm);
            const float al = __expf(mr[r] - mn);
            mr[r] = mn;
            float rs = 0.f;
            #pragma unroll
            for (int nt = 0; nt < 8; nt++) {
                float e0 = __expf(S[nt][2*r]   - mn);
                float e1 = __expf(S[nt][2*r+1] - mn);
                rs += e0 + e1;
                S[nt][2*r] = e0; S[nt][2*r+1] = e1;
                O[nt][2*r] *= al; O[nt][2*r+1] *= al;
            }
            rs += __shfl_xor_sync(0xffffffffu, rs, 1);
            rs += __shfl_xor_sync(0xffffffffu, rs, 2);
            lsum[r] = lsum[r]*al + rs;
        }

        // ---- write P (own-warp rows only) ----
        #pragma unroll
        for (int nt = 0; nt < 8; nt++) {
            const int col = nt*8 + 2*c4;
            *(uint2*)&SP[lrow*64     + (col ^ (r4<<2))] =
                make_uint2(tf32u(S[nt][0]), tf32u(S[nt][1]));
            *(uint2*)&SP[(lrow+8)*64 + (col ^ (r4<<2))] =
                make_uint2(tf32u(S[nt][2]), tf32u(S[nt][3]));
        }
        __syncwarp();                        // intra-warp smem visibility

        // ---- O += P.V ----
        #pragma unroll
        for (int ks = 0; ks < 8; ks++) {
            const int k0 = ks*8;
            unsigned pa[4];
            pa[0] = SP[lrow*64     + ((k0+c4)   ^ (r4<<2))];
            pa[1] = SP[(lrow+8)*64 + ((k0+c4)   ^ (r4<<2))];
            pa[2] = SP[lrow*64     + ((k0+c4+4) ^ (r4<<2))];
            pa[3] = SP[(lrow+8)*64 + ((k0+c4+4) ^ (r4<<2))];
            #pragma unroll
            for (int nt = 0; nt < 8; nt++) {
                unsigned bv[2];
                bv[0] = SV[(k0+c4)*64   + ((nt*8+r4) ^ ( c4   <<2))];
                bv[1] = SV[(k0+c4+4)*64 + ((nt*8+r4) ^ ((c4+4)<<2))];
                MMA_TF32(O[nt], pa, bv);
            }
        }
    }

    // ---- epilogue: normalize / vmean, scrambled reference layout ----
    const int pad0 = (__ldg(mask + b*NT + tq0) == 0);
    const int pad1 = (__ldg(mask + b*NT + tq1) == 0);
    const float il0 = 1.0f / lsum[0], il1 = 1.0f / lsum[1];
    const int rnew0 = h*64 + (tq0 >> 4), cb0 = (tq0 & 15) * 64;
    const int rnew1 = h*64 + (tq1 >> 4), cb1 = (tq1 & 15) * 64;
    #pragma unroll
    for (int nt = 0; nt < 8; nt++) {
        const int s0 = nt*8 + 2*c4;
        float2 o0, o1;
        if (pad0) o0 = *(const float2*)(g_vmean + bh*NS + s0);
        else      o0 = make_float2(O[nt][0]*il0, O[nt][1]*il0);
        if (pad1) o1 = *(const float2*)(g_vmean + bh*NS + s0);
        else      o1 = make_float2(O[nt][2]*il1, O[nt][3]*il1);
        *(float2*)(g_attn + ((size_t)(b*NT + rnew0))*NE + cb0 + s0) = o0;
        *(float2*)(g_attn + ((size_t)(b*NT + rnew1))*NE + cb1 + s0) = o1;
    }
}

// ---------------------------------------------------------------------------
// K5 (tf32 tensor): out = attn @ Wo^T + bo.  M=4096, N=1024, K=1024.
// ---------------------------------------------------------------------------
__global__ __launch_bounds__(256) void out_tf32_kernel(
    const float* __restrict__ Wo, const float* __restrict__ bo,
    float* __restrict__ out)
{
    const int n0 = blockIdx.x * 64;
    const int m0 = blockIdx.y * 128;
    __shared__ unsigned As[8192];   // 128 x 64 tf32
    __shared__ unsigned Bs[4096];   // 64 x 64 tf32
    const int tid = threadIdx.x;
    const int lane = tid & 31, wid = tid >> 5;
    const int mw = wid & 3, nw = wid >> 2;
    const int r4 = lane >> 2, c4 = lane & 3;
    const int swz = r4 << 2;

    float acc[2][4][4] = {};

    for (int kc = 0; kc < 16; kc++) {
        __syncthreads();
        {
            #pragma unroll
            for (int i = 0; i < 8; i++) {
                const int idx = tid + i*256, row = idx >> 4, cb = (idx & 15) * 4;
                float4 v = *(const float4*)(g_attn + (size_t)(m0 + row)*NE + kc*64 + cb);
                *(uint4*)&As[row*64 + (cb ^ ((row & 7) << 2))] =
                    make_uint4(tf32u(v.x), tf32u(v.y), tf32u(v.z), tf32u(v.w));
            }
        }
        {
            #pragma unroll
            for (int i = 0; i < 4; i++) {
                const int idx = tid + i*256, row = idx >> 4, cb = (idx & 15) * 4;
                float4 v = *(const float4*)(Wo + (size_t)(n0 + row)*NE + kc*64 + cb);
                *(uint4*)&Bs[row*64 + (cb ^ ((row & 7) << 2))] =
                    make_uint4(tf32u(v.x), tf32u(v.y), tf32u(v.z), tf32u(v.w));
            }
        }
        __syncthreads();

        #pragma unroll
        for (int ks = 0; ks < 8; ks++) {
            const int k0 = ks * 8;
            unsigned a[2][4], b[4][2];
            #pragma unroll
            for (int mt = 0; mt < 2; mt++) {
                const int base = (mw*32 + mt*16 + r4) * 64;
                a[mt][0] = As[base       + ((k0 + c4)     ^ swz)];
                a[mt][1] = As[base + 512 + ((k0 + c4)     ^ swz)];
                a[mt][2] = As[base       + ((k0 + c4 + 4) ^ swz)];
                a[mt][3] = As[base + 512 + ((k0 + c4 + 4) ^ swz)];
            }
            #pragma unroll
            for (int nt = 0; nt < 4; nt++) {
                const int base = (nw*32 + nt*8 + r4) * 64;
                b[nt][0] = Bs[base + ((k0 + c4)     ^ swz)];
                b[nt][1] = Bs[base + ((k0 + c4 + 4) ^ swz)];
            }
            #pragma unroll
            for (int mt = 0; mt < 2; mt++)
                #pragma unroll
                for (int nt = 0; nt < 4; nt++)
                    MMA_TF32(acc[mt][nt], a[mt], b[nt]);
        }
    }

    #pragma unroll
    for (int mt = 0; mt < 2; mt++) {
        const int ro = m0 + mw*32 + mt*16 + r4;
        #pragma unroll
        for (int nt = 0; nt < 4; nt++) {
            const int co = n0 + nw*32 + nt*8 + c4*2;
            const float b0 = __ldg(bo + co), b1 = __ldg(bo + co + 1);
            *(float2*)(out + (size_t)ro*NE + co) =
                make_float2(acc[mt][nt][0] + b0, acc[mt][nt][1] + b1);
            *(float2*)(out + (size_t)(ro + 8)*NE + co) =
                make_float2(acc[mt][nt][2] + b0, acc[mt][nt][3] + b1);
        }
    }
}

// ---------------------------------------------------------------------------
extern "C" void kernel_launch(void* const* d_in, const int* in_sizes, int n_in,
                              void* d_out, int out_size)
{
    const float* x    = (const float*)d_in[0];
    const int*   mask = (const int*)  d_in[1];
    const float* Wq   = (const float*)d_in[2];
    const float* Wk   = (const float*)d_in[3];
    const float* Wv   = (const float*)d_in[4];
    const float* Er   = (const float*)d_in[5];
    const float* Wo   = (const float*)d_in[6];
    const float* bo   = (const float*)d_in[7];
    float* out = (float*)d_out;

    cudaFuncSetAttribute(attn_tc_kernel,
                         cudaFuncAttributeMaxDynamicSharedMemorySize, 65536);

    proj_kernel<<<1024, 256>>>(x, Wq, Wk, Wv);
    vmean_kernel<<<64, 64>>>();
    qer_tf32_kernel<<<dim3(16, 8, 64), 256>>>(Er);
    attn_tc_kernel<<<dim3(8, 64), 256, 65536>>>(mask);
    out_tf32_kernel<<<dim3(16, 32), 256>>>(Wo, bo, out);
}

// round 16
// speedup vs baseline: 3.0018x; 1.0393x over previous
#include <cuda_runtime.h>

#define NB 4
#define NT 1024
#define NH 16
#define NS 64
#define NE 1024
#define NEGV -1000000000.0f

// Scratch (device globals — allocation-free kernel_launch)
static __device__ float g_Q[NB*NH*NT*NS];
static __device__ float g_K[NB*NH*NT*NS];
static __device__ float g_V[NB*NH*NT*NS];
static __device__ float g_QEr[(size_t)NB*NH*NT*NT];   // only upper band used
static __device__ float g_attn[NB*NT*NE];             // reference's scrambled layout
static __device__ float g_vmean[NB*NH*NS];

// ---------------------------------------------------------------------------
// tf32 helpers (m16n8k8 fragment layout validated on HW in R13/R15)
// ---------------------------------------------------------------------------
__device__ __forceinline__ unsigned tf32u(float x) {
    unsigned u;
    asm("cvt.rna.tf32.f32 %0, %1;" : "=r"(u) : "f"(x));
    return u;
}

#define MMA_TF32(d, a, b)                                                     \
    asm volatile(                                                             \
        "mma.sync.aligned.m16n8k8.row.col.f32.tf32.tf32.f32 "                 \
        "{%0,%1,%2,%3}, {%4,%5,%6,%7}, {%8,%9}, {%0,%1,%2,%3};"               \
        : "+f"((d)[0]), "+f"((d)[1]), "+f"((d)[2]), "+f"((d)[3])              \
        : "r"((a)[0]), "r"((a)[1]), "r"((a)[2]), "r"((a)[3]),                 \
          "r"((b)[0]), "r"((b)[1]))

// ---------------------------------------------------------------------------
// K1: QKV projection (fp32).  x viewed as [65536,64].
// ---------------------------------------------------------------------------
__global__ __launch_bounds__(256) void proj_kernel(
    const float* __restrict__ x, const float* __restrict__ Wq,
    const float* __restrict__ Wk, const float* __restrict__ Wv)
{
    __shared__ float As[4096];   // transposed: As[k*64+m]
    __shared__ float Bs[4096];   // transposed: Bs[k*64+o]
    const int tid = threadIdx.x;
    const int tx = tid & 15, ty = tid >> 4;
    const int m0 = blockIdx.x * 64;
    const int mr = tid >> 2, k0 = (tid & 3) * 16;

    {   // x tile -> As transposed
        const float* xp = x + (size_t)(m0 + mr) * 64 + k0;
        #pragma unroll
        for (int u = 0; u < 4; u++) {
            float4 v = *(const float4*)(xp + u*4);
            As[(k0+u*4+0)*64 + mr] = v.x;
            As[(k0+u*4+1)*64 + mr] = v.y;
            As[(k0+u*4+2)*64 + mr] = v.z;
            As[(k0+u*4+3)*64 + mr] = v.w;
        }
    }

    const float* Ws[3] = {Wq, Wk, Wv};
    float* Os[3] = {g_Q, g_K, g_V};

    for (int w = 0; w < 3; w++) {
        float4 breg[4];
        {
            const float* wp = Ws[w] + mr * 64 + k0;
            #pragma unroll
            for (int u = 0; u < 4; u++) breg[u] = *(const float4*)(wp + u*4);
        }
        __syncthreads();
        #pragma unroll
        for (int u = 0; u < 4; u++) {
            Bs[(k0+u*4+0)*64 + mr] = breg[u].x;
            Bs[(k0+u*4+1)*64 + mr] = breg[u].y;
            Bs[(k0+u*4+2)*64 + mr] = breg[u].z;
            Bs[(k0+u*4+3)*64 + mr] = breg[u].w;
        }
        __syncthreads();
        float acc[4][4] = {};
        #pragma unroll 8
        for (int k = 0; k < 64; k++) {
            float4 a4 = *(const float4*)(As + k*64 + ty*4);
            float4 b4 = *(const float4*)(Bs + k*64 + tx*4);
            acc[0][0] += a4.x*b4.x; acc[0][1] += a4.x*b4.y; acc[0][2] += a4.x*b4.z; acc[0][3] += a4.x*b4.w;
            acc[1][0] += a4.y*b4.x; acc[1][1] += a4.y*b4.y; acc[1][2] += a4.y*b4.z; acc[1][3] += a4.y*b4.w;
            acc[2][0] += a4.z*b4.x; acc[2][1] += a4.z*b4.y; acc[2][2] += a4.z*b4.z; acc[2][3] += a4.z*b4.w;
            acc[3][0] += a4.w*b4.x; acc[3][1] += a4.w*b4.y; acc[3][2] += a4.w*b4.z; acc[3][3] += a4.w*b4.w;
        }
        #pragma unroll
        for (int i = 0; i < 4; i++) {
            const int r = m0 + ty*4 + i;
            const int h = r & 15, t = (r >> 4) & 1023, b = r >> 14;
            float* dst = Os[w] + (((size_t)(b*NH + h))*NT + t)*NS + tx*4;
            *(float4*)dst = make_float4(acc[i][0], acc[i][1], acc[i][2], acc[i][3]);
        }
    }
}

// ---------------------------------------------------------------------------
// K2: per-(b,h) mean of V over all t (padded rows: softmax exactly uniform)
// ---------------------------------------------------------------------------
__global__ __launch_bounds__(64) void vmean_kernel()
{
    const int bh = blockIdx.x;
    const int o  = threadIdx.x;
    const float* vp = g_V + (size_t)bh * NT * NS + o;
    float sum = 0.f;
    for (int t = 0; t < NT; t++) sum += vp[(size_t)t * NS];
    g_vmean[bh * NS + o] = sum * (1.0f / 1024.0f);
}

// ---------------------------------------------------------------------------
// K3 (tf32 tensor): QEr[b,h,tq,l] = Q[b,h,tq,:].Er[h,l,:], band only.
// ---------------------------------------------------------------------------
__global__ __launch_bounds__(256) void qer_tf32_kernel(const float* __restrict__ Er)
{
    const int n0 = blockIdx.x * 64;
    const int m0 = blockIdx.y * 128;
    if (m0 + n0 < 833) return;            // tile never gathered (l >= 1023-tq)
    const int bh = blockIdx.z;
    const int h  = bh & 15;

    __shared__ unsigned As[8192];   // 128 x 64 tf32
    __shared__ unsigned Bs[4096];   // 64 x 64 tf32
    const int tid = threadIdx.x;
    const int lane = tid & 31, wid = tid >> 5;
    const int mw = wid & 3, nw = wid >> 2;         // 4 warps in M, 2 in N
    const int r4 = lane >> 2, c4 = lane & 3;
    const int swz = r4 << 2;

    {
        #pragma unroll
        for (int i = 0; i < 8; i++) {
            const int idx = tid + i*256, row = idx >> 4, cb = (idx & 15) * 4;
            float4 v = *(const float4*)(g_Q + ((size_t)bh*NT + m0 + row)*NS + cb);
            *(uint4*)&As[row*64 + (cb ^ ((row & 7) << 2))] =
                make_uint4(tf32u(v.x), tf32u(v.y), tf32u(v.z), tf32u(v.w));
        }
    }
    {
        #pragma unroll
        for (int i = 0; i < 4; i++) {
            const int idx = tid + i*256, row = idx >> 4, cb = (idx & 15) * 4;
            float4 v = *(const float4*)(Er + ((size_t)h*NT + n0 + row)*NS + cb);
            *(uint4*)&Bs[row*64 + (cb ^ ((row & 7) << 2))] =
                make_uint4(tf32u(v.x), tf32u(v.y), tf32u(v.z), tf32u(v.w));
        }
    }
    __syncthreads();

    float acc[2][4][4] = {};
    #pragma unroll
    for (int ks = 0; ks < 8; ks++) {
        const int k0 = ks * 8;
        unsigned a[2][4], b[4][2];
        #pragma unroll
        for (int mt = 0; mt < 2; mt++) {
            const int base = (mw*32 + mt*16 + r4) * 64;
            a[mt][0] = As[base       + ((k0 + c4)     ^ swz)];
            a[mt][1] = As[base + 512 + ((k0 + c4)     ^ swz)];
            a[mt][2] = As[base       + ((k0 + c4 + 4) ^ swz)];
            a[mt][3] = As[base + 512 + ((k0 + c4 + 4) ^ swz)];
        }
        #pragma unroll
        for (int nt = 0; nt < 4; nt++) {
            const int base = (nw*32 + nt*8 + r4) * 64;
            b[nt][0] = Bs[base + ((k0 + c4)     ^ swz)];
            b[nt][1] = Bs[base + ((k0 + c4 + 4) ^ swz)];
        }
        #pragma unroll
        for (int mt = 0; mt < 2; mt++)
            #pragma unroll
            for (int nt = 0; nt < 4; nt++)
                MMA_TF32(acc[mt][nt], a[mt], b[nt]);
    }

    #pragma unroll
    for (int mt = 0; mt < 2; mt++) {
        const int ro = m0 + mw*32 + mt*16 + r4;
        #pragma unroll
        for (int nt = 0; nt < 4; nt++) {
            const int co = n0 + nw*32 + nt*8 + c4*2;
            *(float2*)(g_QEr + ((size_t)bh*NT + ro)*NT + co) =
                make_float2(acc[mt][nt][0], acc[mt][nt][1]);
            *(float2*)(g_QEr + ((size_t)bh*NT + ro + 8)*NT + co) =
                make_float2(acc[mt][nt][2], acc[mt][nt][3]);
        }
    }
}

// ---------------------------------------------------------------------------
// K4 (tensor-core flash attn, 2 blocks/SM): M=128/block, N=64/ktile.
// Q frags re-read from dedicated SQ region (saves 32 regs -> occupancy 2).
// smem: SQ(8192w) | SP(8192w, P tiles) | SK(4096w) | SV(4096w) = 96KB.
// Heavy causal tiles scheduled first (mtile = 7 - blockIdx.x).
// ---------------------------------------------------------------------------
__global__ __launch_bounds__(256, 2) void attn_tc_kernel(const int* __restrict__ mask)
{
    extern __shared__ unsigned sm[];
    unsigned* SQ = sm;            // 8192 words: Q (tf32, scaled)
    unsigned* SP = sm + 8192;     // 8192 words: P
    unsigned* SK = sm + 16384;    // 4096 words: K tile
    unsigned* SV = sm + 20480;    // 4096 words: V tile

    const int tid = threadIdx.x;
    const int lane = tid & 31, w = tid >> 5;
    const int r4 = lane >> 2, c4 = lane & 3;
    const int bh = blockIdx.y, b = bh >> 4, h = bh & 15;
    const int mtile = 7 - (int)blockIdx.x;     // heavy blocks launch first
    const int m0 = mtile * 128;

    {   // stage Q (scaled by 1/32, tf32, swizzled)
        const float inv = 0.03125f;
        #pragma unroll
        for (int i = 0; i < 8; i++) {
            const int idx = tid + i*256, row = idx >> 4, cb = (idx & 15) * 4;
            float4 v = *(const float4*)(g_Q + ((size_t)bh*NT + m0 + row)*NS + cb);
            *(uint4*)&SQ[row*64 + (cb ^ ((row & 7) << 2))] =
                make_uint4(tf32u(v.x*inv), tf32u(v.y*inv), tf32u(v.z*inv), tf32u(v.w*inv));
        }
    }
    __syncthreads();

    const int lrow = w*16 + r4;                 // local row (0..127), row&7 == r4
    const int tq0 = m0 + lrow, tq1 = tq0 + 8;
    const float* qer0 = g_QEr + ((size_t)bh*NT + tq0)*NT + (1023 - tq0);
    const float* qer1 = g_QEr + ((size_t)bh*NT + tq1)*NT + (1023 - tq1);

    float O[8][4] = {};
    float mr[2] = {-1e30f, -1e30f};
    float lsum[2] = {0.f, 0.f};

    const int nkt = 2*mtile + 2;
    for (int kt = 0; kt < nkt; kt++) {
        const int n0 = kt*64;
        __syncthreads();                      // prev PV reads of SK/SV done
        {   // stage K and V tiles (tf32, swizzled)
            #pragma unroll
            for (int i = 0; i < 4; i++) {
                const int idx = tid + i*256, row = idx >> 4, cb = (idx & 15) * 4;
                const int so = row*64 + (cb ^ ((row & 7) << 2));
                float4 kv = *(const float4*)(g_K + ((size_t)bh*NT + n0 + row)*NS + cb);
                *(uint4*)&SK[so] = make_uint4(tf32u(kv.x), tf32u(kv.y), tf32u(kv.z), tf32u(kv.w));
                float4 vv = *(const float4*)(g_V + ((size_t)bh*NT + n0 + row)*NS + cb);
                *(uint4*)&SV[so] = make_uint4(tf32u(vv.x), tf32u(vv.y), tf32u(vv.z), tf32u(vv.w));
            }
        }
        __syncthreads();

        // ---- S = Q.K^T (Q frags from SQ per k-step) ----
        float S[8][4] = {};
        #pragma unroll
        for (int ks = 0; ks < 8; ks++) {
            const int k0 = ks*8;
            unsigned qa[4];
            qa[0] = SQ[lrow*64     + ((k0+c4)   ^ (r4<<2))];
            qa[1] = SQ[(lrow+8)*64 + ((k0+c4)   ^ (r4<<2))];
            qa[2] = SQ[lrow*64     + ((k0+c4+4) ^ (r4<<2))];
            qa[3] = SQ[(lrow+8)*64 + ((k0+c4+4) ^ (r4<<2))];
            unsigned bb[8][2];
            #pragma unroll
            for (int nt = 0; nt < 8; nt++) {
                const int base = (nt*8 + r4)*64;
                bb[nt][0] = SK[base + ((k0+c4)   ^ (r4<<2))];
                bb[nt][1] = SK[base + ((k0+c4+4) ^ (r4<<2))];
            }
            #pragma unroll
            for (int nt = 0; nt < 8; nt++) MMA_TF32(S[nt], qa, bb[nt]);
        }

        // ---- bias + causal (accumulator layout) ----
        #pragma unroll
        for (int nt = 0; nt < 8; nt++) {
            const int tk = n0 + nt*8 + c4*2;
            S[nt][0] = (tk   <= tq0) ? S[nt][0] + __ldg(qer0+tk)   : NEGV;
            S[nt][1] = (tk+1 <= tq0) ? S[nt][1] + __ldg(qer0+tk+1) : NEGV;
            S[nt][2] = (tk   <= tq1) ? S[nt][2] + __ldg(qer1+tk)   : NEGV;
            S[nt][3] = (tk+1 <= tq1) ? S[nt][3] + __ldg(qer1+tk+1) : NEGV;
        }

        // ---- online softmax (rows r4 / r4+8); lanes of a row differ in c4 ----
        #pragma unroll
        for (int r = 0; r < 2; r++) {
            float rm = S[0][2*r];
            #pragma unroll
            for (int nt = 0; nt < 8; nt++)
                rm = fmaxf(rm, fmaxf(S[nt][2*r], S[nt][2*r+1]));
            rm = fmaxf(rm, __shfl_xor_sync(0xffffffffu, rm, 1));
            rm = fmaxf(rm, __shfl_xor_sync(0xffffffffu, rm, 2));
            const float mn = fmaxf(mr[r], rm);
            const float al = __expf(mr[r] - mn);
            mr[r] = mn;
            float rs = 0.f;
            #pragma unroll
            for (int nt = 0; nt < 8; nt++) {
                float e0 = __expf(S[nt][2*r]   - mn);
                float e1 = __expf(S[nt][2*r+1] - mn);
                rs += e0 + e1;
                S[nt][2*r] = e0; S[nt][2*r+1] = e1;
                O[nt][2*r] *= al; O[nt][2*r+1] *= al;
            }
            rs += __shfl_xor_sync(0xffffffffu, rs, 1);
            rs += __shfl_xor_sync(0xffffffffu, rs, 2);
            lsum[r] = lsum[r]*al + rs;
        }

        // ---- write P (own-warp rows only) ----
        #pragma unroll
        for (int nt = 0; nt < 8; nt++) {
            const int col = nt*8 + 2*c4;
            *(uint2*)&SP[lrow*64     + (col ^ (r4<<2))] =
                make_uint2(tf32u(S[nt][0]), tf32u(S[nt][1]));
            *(uint2*)&SP[(lrow+8)*64 + (col ^ (r4<<2))] =
                make_uint2(tf32u(S[nt][2]), tf32u(S[nt][3]));
        }
        __syncwarp();                        // intra-warp smem visibility

        // ---- O += P.V ----
        #pragma unroll
        for (int ks = 0; ks < 8; ks++) {
            const int k0 = ks*8;
            unsigned pa[4];
            pa[0] = SP[lrow*64     + ((k0+c4)   ^ (r4<<2))];
            pa[1] = SP[(lrow+8)*64 + ((k0+c4)   ^ (r4<<2))];
            pa[2] = SP[lrow*64     + ((k0+c4+4) ^ (r4<<2))];
            pa[3] = SP[(lrow+8)*64 + ((k0+c4+4) ^ (r4<<2))];
            #pragma unroll
            for (int nt = 0; nt < 8; nt++) {
                unsigned bv[2];
                bv[0] = SV[(k0+c4)*64   + ((nt*8+r4) ^ ( c4   <<2))];
                bv[1] = SV[(k0+c4+4)*64 + ((nt*8+r4) ^ ((c4+4)<<2))];
                MMA_TF32(O[nt], pa, bv);
            }
        }
    }

    // ---- epilogue: normalize / vmean, scrambled reference layout ----
    const int pad0 = (__ldg(mask + b*NT + tq0) == 0);
    const int pad1 = (__ldg(mask + b*NT + tq1) == 0);
    const float il0 = 1.0f / lsum[0], il1 = 1.0f / lsum[1];
    const int rnew0 = h*64 + (tq0 >> 4), cb0 = (tq0 & 15) * 64;
    const int rnew1 = h*64 + (tq1 >> 4), cb1 = (tq1 & 15) * 64;
    #pragma unroll
    for (int nt = 0; nt < 8; nt++) {
        const int s0 = nt*8 + 2*c4;
        float2 o0, o1;
        if (pad0) o0 = *(const float2*)(g_vmean + bh*NS + s0);
        else      o0 = make_float2(O[nt][0]*il0, O[nt][1]*il0);
        if (pad1) o1 = *(const float2*)(g_vmean + bh*NS + s0);
        else      o1 = make_float2(O[nt][2]*il1, O[nt][3]*il1);
        *(float2*)(g_attn + ((size_t)(b*NT + rnew0))*NE + cb0 + s0) = o0;
        *(float2*)(g_attn + ((size_t)(b*NT + rnew1))*NE + cb1 + s0) = o1;
    }
}

// ---------------------------------------------------------------------------
// K5 (tf32 tensor): out = attn @ Wo^T + bo.  M=4096, N=1024, K=1024.
// ---------------------------------------------------------------------------
__global__ __launch_bounds__(256) void out_tf32_kernel(
    const float* __restrict__ Wo, const float* __restrict__ bo,
    float* __restrict__ out)
{
    const int n0 = blockIdx.x * 64;
    const int m0 = blockIdx.y * 128;
    __shared__ unsigned As[8192];   // 128 x 64 tf32
    __shared__ unsigned Bs[4096];   // 64 x 64 tf32
    const int tid = threadIdx.x;
    const int lane = tid & 31, wid = tid >> 5;
    const int mw = wid & 3, nw = wid >> 2;
    const int r4 = lane >> 2, c4 = lane & 3;
    const int swz = r4 << 2;

    float acc[2][4][4] = {};

    for (int kc = 0; kc < 16; kc++) {
        __syncthreads();
        {
            #pragma unroll
            for (int i = 0; i < 8; i++) {
                const int idx = tid + i*256, row = idx >> 4, cb = (idx & 15) * 4;
                float4 v = *(const float4*)(g_attn + (size_t)(m0 + row)*NE + kc*64 + cb);
                *(uint4*)&As[row*64 + (cb ^ ((row & 7) << 2))] =
                    make_uint4(tf32u(v.x), tf32u(v.y), tf32u(v.z), tf32u(v.w));
            }
        }
        {
            #pragma unroll
            for (int i = 0; i < 4; i++) {
                const int idx = tid + i*256, row = idx >> 4, cb = (idx & 15) * 4;
                float4 v = *(const float4*)(Wo + (size_t)(n0 + row)*NE + kc*64 + cb);
                *(uint4*)&Bs[row*64 + (cb ^ ((row & 7) << 2))] =
                    make_uint4(tf32u(v.x), tf32u(v.y), tf32u(v.z), tf32u(v.w));
            }
        }
        __syncthreads();

        #pragma unroll
        for (int ks = 0; ks < 8; ks++) {
            const int k0 = ks * 8;
            unsigned a[2][4], b[4][2];
            #pragma unroll
            for (int mt = 0; mt < 2; mt++) {
                const int base = (mw*32 + mt*16 + r4) * 64;
                a[mt][0] = As[base       + ((k0 + c4)     ^ swz)];
                a[mt][1] = As[base + 512 + ((k0 + c4)     ^ swz)];
                a[mt][2] = As[base       + ((k0 + c4 + 4) ^ swz)];
                a[mt][3] = As[base + 512 + ((k0 + c4 + 4) ^ swz)];
            }
            #pragma unroll
            for (int nt = 0; nt < 4; nt++) {
                const int base = (nw*32 + nt*8 + r4) * 64;
                b[nt][0] = Bs[base + ((k0 + c4)     ^ swz)];
                b[nt][1] = Bs[base + ((k0 + c4 + 4) ^ swz)];
            }
            #pragma unroll
            for (int mt = 0; mt < 2; mt++)
                #pragma unroll
                for (int nt = 0; nt < 4; nt++)
                    MMA_TF32(acc[mt][nt], a[mt], b[nt]);
        }
    }

    #pragma unroll
    for (int mt = 0; mt < 2; mt++) {
        const int ro = m0 + mw*32 + mt*16 + r4;
        #pragma unroll
        for (int nt = 0; nt < 4; nt++) {
            const int co = n0 + nw*32 + nt*8 + c4*2;
            const float b0 = __ldg(bo + co), b1 = __ldg(bo + co + 1);
            *(float2*)(out + (size_t)ro*NE + co) =
                make_float2(acc[mt][nt][0] + b0, acc[mt][nt][1] + b1);
            *(float2*)(out + (size_t)(ro + 8)*NE + co) =
                make_float2(acc[mt][nt][2] + b0, acc[mt][nt][3] + b1);
        }
    }
}

// ---------------------------------------------------------------------------
extern "C" void kernel_launch(void* const* d_in, const int* in_sizes, int n_in,
                              void* d_out, int out_size)
{
    const float* x    = (const float*)d_in[0];
    const int*   mask = (const int*)  d_in[1];
    const float* Wq   = (const float*)d_in[2];
    const float* Wk   = (const float*)d_in[3];
    const float* Wv   = (const float*)d_in[4];
    const float* Er   = (const float*)d_in[5];
    const float* Wo   = (const float*)d_in[6];
    const float* bo   = (const float*)d_in[7];
    float* out = (float*)d_out;

    cudaFuncSetAttribute(attn_tc_kernel,
                         cudaFuncAttributeMaxDynamicSharedMemorySize, 98304);

    proj_kernel<<<1024, 256>>>(x, Wq, Wk, Wv);
    vmean_kernel<<<64, 64>>>();
    qer_tf32_kernel<<<dim3(16, 8, 64), 256>>>(Er);
    attn_tc_kernel<<<dim3(8, 64), 256, 98304>>>(mask);
    out_tf32_kernel<<<dim3(16, 32), 256>>>(Wo, bo, out);
}

// round 17
// speedup vs baseline: 3.0309x; 1.0097x over previous
#include <cuda_runtime.h>

#define NB 4
#define NT 1024
#define NH 16
#define NS 64
#define NE 1024
#define NEGV -1000000000.0f

// Scratch (device globals — allocation-free kernel_launch)
static __device__ float g_Q[NB*NH*NT*NS];
static __device__ float g_K[NB*NH*NT*NS];
static __device__ float g_V[NB*NH*NT*NS];
static __device__ float g_QEr[(size_t)NB*NH*NT*NT];   // only upper band used
static __device__ float g_attn[NB*NT*NE];             // reference's scrambled layout
static __device__ float g_vmean[NB*NH*NS];

// ---------------------------------------------------------------------------
// tf32 helpers (m16n8k8 fragment layout validated on HW in R13/R15/R16)
// ---------------------------------------------------------------------------
__device__ __forceinline__ unsigned tf32u(float x) {
    unsigned u;
    asm("cvt.rna.tf32.f32 %0, %1;" : "=r"(u) : "f"(x));
    return u;
}

#define MMA_TF32(d, a, b)                                                     \
    asm volatile(                                                             \
        "mma.sync.aligned.m16n8k8.row.col.f32.tf32.tf32.f32 "                 \
        "{%0,%1,%2,%3}, {%4,%5,%6,%7}, {%8,%9}, {%0,%1,%2,%3};"               \
        : "+f"((d)[0]), "+f"((d)[1]), "+f"((d)[2]), "+f"((d)[3])              \
        : "r"((a)[0]), "r"((a)[1]), "r"((a)[2]), "r"((a)[3]),                 \
          "r"((b)[0]), "r"((b)[1]))

#define CP_ASYNC16(saddr, gptr)                                               \
    asm volatile("cp.async.ca.shared.global [%0], [%1], 16;"                  \
                 :: "r"(saddr), "l"(gptr))
#define CP_COMMIT() asm volatile("cp.async.commit_group;")
#define CP_WAIT(N)  asm volatile("cp.async.wait_group %0;" :: "n"(N))

// ---------------------------------------------------------------------------
// K1 (tf32 tensor): QKV projection.  x viewed as [65536,64]; 3 weights looped.
// ---------------------------------------------------------------------------
__global__ __launch_bounds__(256) void proj_tf32_kernel(
    const float* __restrict__ x, const float* __restrict__ Wq,
    const float* __restrict__ Wk, const float* __restrict__ Wv)
{
    __shared__ unsigned As[8192];   // 128 x 64 tf32 (x rows)
    __shared__ unsigned Bs[4096];   // 64 x 64 tf32 (W rows)
    const int tid = threadIdx.x;
    const int lane = tid & 31, wid = tid >> 5;
    const int mw = wid & 3, nw = wid >> 2;
    const int r4 = lane >> 2, c4 = lane & 3;
    const int swz = r4 << 2;
    const int m0 = blockIdx.x * 128;

    {
        #pragma unroll
        for (int i = 0; i < 8; i++) {
            const int idx = tid + i*256, row = idx >> 4, cb = (idx & 15) * 4;
            float4 v = *(const float4*)(x + (size_t)(m0 + row)*64 + cb);
            *(uint4*)&As[row*64 + (cb ^ ((row & 7) << 2))] =
                make_uint4(tf32u(v.x), tf32u(v.y), tf32u(v.z), tf32u(v.w));
        }
    }

    const float* Ws[3] = {Wq, Wk, Wv};
    float* Os[3] = {g_Q, g_K, g_V};

    for (int w = 0; w < 3; w++) {
        __syncthreads();                      // prev Bs reads done; As ready
        {
            #pragma unroll
            for (int i = 0; i < 4; i++) {
                const int idx = tid + i*256, row = idx >> 4, cb = (idx & 15) * 4;
                float4 v = *(const float4*)(Ws[w] + (size_t)row*64 + cb);
                *(uint4*)&Bs[row*64 + (cb ^ ((row & 7) << 2))] =
                    make_uint4(tf32u(v.x), tf32u(v.y), tf32u(v.z), tf32u(v.w));
            }
        }
        __syncthreads();

        float acc[2][4][4] = {};
        #pragma unroll
        for (int ks = 0; ks < 8; ks++) {
            const int k0 = ks * 8;
            unsigned a[2][4], b[4][2];
            #pragma unroll
            for (int mt = 0; mt < 2; mt++) {
                const int base = (mw*32 + mt*16 + r4) * 64;
                a[mt][0] = As[base       + ((k0 + c4)     ^ swz)];
                a[mt][1] = As[base + 512 + ((k0 + c4)     ^ swz)];
                a[mt][2] = As[base       + ((k0 + c4 + 4) ^ swz)];
                a[mt][3] = As[base + 512 + ((k0 + c4 + 4) ^ swz)];
            }
            #pragma unroll
            for (int nt = 0; nt < 4; nt++) {
                const int base = (nw*32 + nt*8 + r4) * 64;
                b[nt][0] = Bs[base + ((k0 + c4)     ^ swz)];
                b[nt][1] = Bs[base + ((k0 + c4 + 4) ^ swz)];
            }
            #pragma unroll
            for (int mt = 0; mt < 2; mt++)
                #pragma unroll
                for (int nt = 0; nt < 4; nt++)
                    MMA_TF32(acc[mt][nt], a[mt], b[nt]);
        }

        #pragma unroll
        for (int mt = 0; mt < 2; mt++) {
            const int r0 = m0 + mw*32 + mt*16 + r4;
            const int r1 = r0 + 8;
            #pragma unroll
            for (int nt = 0; nt < 4; nt++) {
                const int co = nw*32 + nt*8 + c4*2;
                {
                    const int h = r0 & 15, t = (r0 >> 4) & 1023, b = r0 >> 14;
                    *(float2*)(Os[w] + (((size_t)(b*NH + h))*NT + t)*NS + co) =
                        make_float2(acc[mt][nt][0], acc[mt][nt][1]);
                }
                {
                    const int h = r1 & 15, t = (r1 >> 4) & 1023, b = r1 >> 14;
                    *(float2*)(Os[w] + (((size_t)(b*NH + h))*NT + t)*NS + co) =
                        make_float2(acc[mt][nt][2], acc[mt][nt][3]);
                }
            }
        }
    }
}

// ---------------------------------------------------------------------------
// K2: per-(b,h) mean of V over all t; 256 threads, 4-way split + reduce.
// ---------------------------------------------------------------------------
__global__ __launch_bounds__(256) void vmean_kernel()
{
    __shared__ float red[256];
    const int bh = blockIdx.x;
    const int tid = threadIdx.x;
    const int o = tid & 63, qt = tid >> 6;
    const float* vp = g_V + (size_t)bh * NT * NS + (size_t)qt * 256 * NS + o;
    float sum = 0.f;
    #pragma unroll 8
    for (int t = 0; t < 256; t++) sum += vp[(size_t)t * NS];
    red[tid] = sum;
    __syncthreads();
    if (tid < 64)
        g_vmean[bh * NS + tid] = (red[tid] + red[tid+64] + red[tid+128] + red[tid+192])
                                 * (1.0f / 1024.0f);
}

// ---------------------------------------------------------------------------
// K3 (tf32 tensor): QEr[b,h,tq,l] = Q[b,h,tq,:].Er[h,l,:], band only.
// ---------------------------------------------------------------------------
__global__ __launch_bounds__(256) void qer_tf32_kernel(const float* __restrict__ Er)
{
    const int n0 = blockIdx.x * 64;
    const int m0 = blockIdx.y * 128;
    if (m0 + n0 < 833) return;            // tile never gathered (l >= 1023-tq)
    const int bh = blockIdx.z;
    const int h  = bh & 15;

    __shared__ unsigned As[8192];   // 128 x 64 tf32
    __shared__ unsigned Bs[4096];   // 64 x 64 tf32
    const int tid = threadIdx.x;
    const int lane = tid & 31, wid = tid >> 5;
    const int mw = wid & 3, nw = wid >> 2;         // 4 warps in M, 2 in N
    const int r4 = lane >> 2, c4 = lane & 3;
    const int swz = r4 << 2;

    {
        #pragma unroll
        for (int i = 0; i < 8; i++) {
            const int idx = tid + i*256, row = idx >> 4, cb = (idx & 15) * 4;
            float4 v = *(const float4*)(g_Q + ((size_t)bh*NT + m0 + row)*NS + cb);
            *(uint4*)&As[row*64 + (cb ^ ((row & 7) << 2))] =
                make_uint4(tf32u(v.x), tf32u(v.y), tf32u(v.z), tf32u(v.w));
        }
    }
    {
        #pragma unroll
        for (int i = 0; i < 4; i++) {
            const int idx = tid + i*256, row = idx >> 4, cb = (idx & 15) * 4;
            float4 v = *(const float4*)(Er + ((size_t)h*NT + n0 + row)*NS + cb);
            *(uint4*)&Bs[row*64 + (cb ^ ((row & 7) << 2))] =
                make_uint4(tf32u(v.x), tf32u(v.y), tf32u(v.z), tf32u(v.w));
        }
    }
    __syncthreads();

    float acc[2][4][4] = {};
    #pragma unroll
    for (int ks = 0; ks < 8; ks++) {
        const int k0 = ks * 8;
        unsigned a[2][4], b[4][2];
        #pragma unroll
        for (int mt = 0; mt < 2; mt++) {
            const int base = (mw*32 + mt*16 + r4) * 64;
            a[mt][0] = As[base       + ((k0 + c4)     ^ swz)];
            a[mt][1] = As[base + 512 + ((k0 + c4)     ^ swz)];
            a[mt][2] = As[base       + ((k0 + c4 + 4) ^ swz)];
            a[mt][3] = As[base + 512 + ((k0 + c4 + 4) ^ swz)];
        }
        #pragma unroll
        for (int nt = 0; nt < 4; nt++) {
            const int base = (nw*32 + nt*8 + r4) * 64;
            b[nt][0] = Bs[base + ((k0 + c4)     ^ swz)];
            b[nt][1] = Bs[base + ((k0 + c4 + 4) ^ swz)];
        }
        #pragma unroll
        for (int mt = 0; mt < 2; mt++)
            #pragma unroll
            for (int nt = 0; nt < 4; nt++)
                MMA_TF32(acc[mt][nt], a[mt], b[nt]);
    }

    #pragma unroll
    for (int mt = 0; mt < 2; mt++) {
        const int ro = m0 + mw*32 + mt*16 + r4;
        #pragma unroll
        for (int nt = 0; nt < 4; nt++) {
            const int co = n0 + nw*32 + nt*8 + c4*2;
            *(float2*)(g_QEr + ((size_t)bh*NT + ro)*NT + co) =
                make_float2(acc[mt][nt][0], acc[mt][nt][1]);
            *(float2*)(g_QEr + ((size_t)bh*NT + ro + 8)*NT + co) =
                make_float2(acc[mt][nt][2], acc[mt][nt][3]);
        }
    }
}

// ---------------------------------------------------------------------------
// K4 (tensor-core flash attn, cp.async pipelined, 2 blocks/SM):
// smem: SQ(8192w) | SP(8192w) | SK ping/pong (2x4096w) | SV(4096w) = 112KB.
// Q/K/V staged as RAW fp32 bits (HW tf32-truncates); scale 1/32 applied to S.
// K double-buffered: K(i+1) issued at tile-i start; V(i) overlaps qk+softmax.
// ---------------------------------------------------------------------------
__global__ __launch_bounds__(256, 2) void attn_tc_kernel(const int* __restrict__ mask)
{
    extern __shared__ unsigned sm[];
    unsigned* SP = sm + 8192;     // P tiles
    unsigned* SV = sm + 24576;    // V tile
    const unsigned sbase = (unsigned)__cvta_generic_to_shared(sm);

    const int tid = threadIdx.x;
    const int lane = tid & 31, w = tid >> 5;
    const int r4 = lane >> 2, c4 = lane & 3;
    const int bh = blockIdx.y, b = bh >> 4, h = bh & 15;
    const int mtile = 7 - (int)blockIdx.x;     // heavy blocks launch first
    const int m0 = mtile * 128;
    const int nkt = 2*mtile + 2;

    // per-thread staging coords (16B chunks)
    const int srow  = (tid + 0*256) >> 4;          // pattern rows: tid>>4 + i*16
    const int scb   = (tid & 15) * 4;

    {   // prefetch Q (8 chunks) + K(0) (4 chunks) in one async group
        #pragma unroll
        for (int i = 0; i < 8; i++) {
            const int row = srow + i*16;
            const int so = row*64 + (scb ^ ((row & 7) << 2));
            CP_ASYNC16(sbase + so*4, g_Q + ((size_t)bh*NT + m0 + row)*NS + scb);
        }
        #pragma unroll
        for (int i = 0; i < 4; i++) {
            const int row = srow + i*16;
            const int so = 16384 + row*64 + (scb ^ ((row & 7) << 2));
            CP_ASYNC16(sbase + so*4, g_K + ((size_t)bh*NT + row)*NS + scb);
        }
        CP_COMMIT();
    }

    const int lrow = w*16 + r4;                 // local row (0..127), row&7 == r4
    const int tq0 = m0 + lrow, tq1 = tq0 + 8;
    const float* qer0 = g_QEr + ((size_t)bh*NT + tq0)*NT + (1023 - tq0);
    const float* qer1 = g_QEr + ((size_t)bh*NT + tq1)*NT + (1023 - tq1);

    float O[8][4] = {};
    float mr[2] = {-1e30f, -1e30f};
    float lsum[2] = {0.f, 0.f};

    for (int kt = 0; kt < nkt; kt++) {
        const int n0 = kt*64;
        const unsigned* SK = sm + 16384 + (kt & 1)*4096;

        CP_WAIT(0);                           // K(kt) (and Q on kt==0) arrived
        __syncthreads();                      // ..for all threads; prev PV done

        {   // issue V(kt) -> SV (overlaps qk + softmax)
            #pragma unroll
            for (int i = 0; i < 4; i++) {
                const int row = srow + i*16;
                const int so = 24576 + row*64 + (scb ^ ((row & 7) << 2));
                CP_ASYNC16(sbase + so*4, g_V + ((size_t)bh*NT + n0 + row)*NS + scb);
            }
            CP_COMMIT();
        }
        if (kt + 1 < nkt) {                   // issue K(kt+1) -> other buffer
            #pragma unroll
            for (int i = 0; i < 4; i++) {
                const int row = srow + i*16;
                const int so = 16384 + ((kt+1) & 1)*4096 + row*64 + (scb ^ ((row & 7) << 2));
                CP_ASYNC16(sbase + so*4, g_K + ((size_t)bh*NT + n0 + 64 + row)*NS + scb);
            }
        }
        CP_COMMIT();                          // (possibly empty) group for K(kt+1)

        // ---- S = Q.K^T (raw-fp32 operands, HW truncates to tf32) ----
        float S[8][4] = {};
        #pragma unroll
        for (int ks = 0; ks < 8; ks++) {
            const int k0 = ks*8;
            unsigned qa[4];
            qa[0] = sm[lrow*64     + ((k0+c4)   ^ (r4<<2))];
            qa[1] = sm[(lrow+8)*64 + ((k0+c4)   ^ (r4<<2))];
            qa[2] = sm[lrow*64     + ((k0+c4+4) ^ (r4<<2))];
            qa[3] = sm[(lrow+8)*64 + ((k0+c4+4) ^ (r4<<2))];
            unsigned bb[8][2];
            #pragma unroll
            for (int nt = 0; nt < 8; nt++) {
                const int base = (nt*8 + r4)*64;
                bb[nt][0] = SK[base + ((k0+c4)   ^ (r4<<2))];
                bb[nt][1] = SK[base + ((k0+c4+4) ^ (r4<<2))];
            }
            #pragma unroll
            for (int nt = 0; nt < 8; nt++) MMA_TF32(S[nt], qa, bb[nt]);
        }

        // ---- scale (1/32) + bias + causal (accumulator layout) ----
        const float sc = 0.03125f;
        #pragma unroll
        for (int nt = 0; nt < 8; nt++) {
            const int tk = n0 + nt*8 + c4*2;
            S[nt][0] = (tk   <= tq0) ? fmaf(S[nt][0], sc, __ldg(qer0+tk))   : NEGV;
            S[nt][1] = (tk+1 <= tq0) ? fmaf(S[nt][1], sc, __ldg(qer0+tk+1)) : NEGV;
            S[nt][2] = (tk   <= tq1) ? fmaf(S[nt][2], sc, __ldg(qer1+tk))   : NEGV;
            S[nt][3] = (tk+1 <= tq1) ? fmaf(S[nt][3], sc, __ldg(qer1+tk+1)) : NEGV;
        }

        // ---- online softmax (rows r4 / r4+8); lanes of a row differ in c4 ----
        #pragma unroll
        for (int r = 0; r < 2; r++) {
            float rm = S[0][2*r];
            #pragma unroll
            for (int nt = 0; nt < 8; nt++)
                rm = fmaxf(rm, fmaxf(S[nt][2*r], S[nt][2*r+1]));
            rm = fmaxf(rm, __shfl_xor_sync(0xffffffffu, rm, 1));
            rm = fmaxf(rm, __shfl_xor_sync(0xffffffffu, rm, 2));
            const float mn = fmaxf(mr[r], rm);
            const float al = __expf(mr[r] - mn);
            mr[r] = mn;
            float rs = 0.f;
            #pragma unroll
            for (int nt = 0; nt < 8; nt++) {
                float e0 = __expf(S[nt][2*r]   - mn);
                float e1 = __expf(S[nt][2*r+1] - mn);
                rs += e0 + e1;
                S[nt][2*r] = e0; S[nt][2*r+1] = e1;
                O[nt][2*r] *= al; O[nt][2*r+1] *= al;
            }
            rs += __shfl_xor_sync(0xffffffffu, rs, 1);
            rs += __shfl_xor_sync(0xffffffffu, rs, 2);
            lsum[r] = lsum[r]*al + rs;
        }

        // ---- write P (own-warp rows only; RNA cvt) ----
        #pragma unroll
        for (int nt = 0; nt < 8; nt++) {
            const int col = nt*8 + 2*c4;
            *(uint2*)&SP[lrow*64     + (col ^ (r4<<2))] =
                make_uint2(tf32u(S[nt][0]), tf32u(S[nt][1]));
            *(uint2*)&SP[(lrow+8)*64 + (col ^ (r4<<2))] =
                make_uint2(tf32u(S[nt][2]), tf32u(S[nt][3]));
        }
        __syncwarp();                        // intra-warp smem visibility

        CP_WAIT(1);                          // V(kt) done (K(kt+1) may fly)
        __syncthreads();                     // ..for all threads

        // ---- O += P.V ----
        #pragma unroll
        for (int ks = 0; ks < 8; ks++) {
            const int k0 = ks*8;
            unsigned pa[4];
            pa[0] = SP[lrow*64     + ((k0+c4)   ^ (r4<<2))];
            pa[1] = SP[(lrow+8)*64 + ((k0+c4)   ^ (r4<<2))];
            pa[2] = SP[lrow*64     + ((k0+c4+4) ^ (r4<<2))];
            pa[3] = SP[(lrow+8)*64 + ((k0+c4+4) ^ (r4<<2))];
            #pragma unroll
            for (int nt = 0; nt < 8; nt++) {
                unsigned bv[2];
                bv[0] = SV[(k0+c4)*64   + ((nt*8+r4) ^ ( c4   <<2))];
                bv[1] = SV[(k0+c4+4)*64 + ((nt*8+r4) ^ ((c4+4)<<2))];
                MMA_TF32(O[nt], pa, bv);
            }
        }
    }

    // ---- epilogue: normalize / vmean, scrambled reference layout ----
    const int pad0 = (__ldg(mask + b*NT + tq0) == 0);
    const int pad1 = (__ldg(mask + b*NT + tq1) == 0);
    const float il0 = 1.0f / lsum[0], il1 = 1.0f / lsum[1];
    const int rnew0 = h*64 + (tq0 >> 4), cb0 = (tq0 & 15) * 64;
    const int rnew1 = h*64 + (tq1 >> 4), cb1 = (tq1 & 15) * 64;
    #pragma unroll
    for (int nt = 0; nt < 8; nt++) {
        const int s0 = nt*8 + 2*c4;
        float2 o0, o1;
        if (pad0) o0 = *(const float2*)(g_vmean + bh*NS + s0);
        else      o0 = make_float2(O[nt][0]*il0, O[nt][1]*il0);
        if (pad1) o1 = *(const float2*)(g_vmean + bh*NS + s0);
        else      o1 = make_float2(O[nt][2]*il1, O[nt][3]*il1);
        *(float2*)(g_attn + ((size_t)(b*NT + rnew0))*NE + cb0 + s0) = o0;
        *(float2*)(g_attn + ((size_t)(b*NT + rnew1))*NE + cb1 + s0) = o1;
    }
}

// ---------------------------------------------------------------------------
// K5 (tf32 tensor): out = attn @ Wo^T + bo.  M=4096, N=1024, K=1024.
// ---------------------------------------------------------------------------
__global__ __launch_bounds__(256) void out_tf32_kernel(
    const float* __restrict__ Wo, const float* __restrict__ bo,
    float* __restrict__ out)
{
    const int n0 = blockIdx.x * 64;
    const int m0 = blockIdx.y * 128;
    __shared__ unsigned As[8192];   // 128 x 64 tf32
    __shared__ unsigned Bs[4096];   // 64 x 64 tf32
    const int tid = threadIdx.x;
    const int lane = tid & 31, wid = tid >> 5;
    const int mw = wid & 3, nw = wid >> 2;
    const int r4 = lane >> 2, c4 = lane & 3;
    const int swz = r4 << 2;

    float acc[2][4][4] = {};

    for (int kc = 0; kc < 16; kc++) {
        __syncthreads();
        {
            #pragma unroll
            for (int i = 0; i < 8; i++) {
                const int idx = tid + i*256, row = idx >> 4, cb = (idx & 15) * 4;
                float4 v = *(const float4*)(g_attn + (size_t)(m0 + row)*NE + kc*64 + cb);
                *(uint4*)&As[row*64 + (cb ^ ((row & 7) << 2))] =
                    make_uint4(tf32u(v.x), tf32u(v.y), tf32u(v.z), tf32u(v.w));
            }
        }
        {
            #pragma unroll
            for (int i = 0; i < 4; i++) {
                const int idx = tid + i*256, row = idx >> 4, cb = (idx & 15) * 4;
                float4 v = *(const float4*)(Wo + (size_t)(n0 + row)*NE + kc*64 + cb);
                *(uint4*)&Bs[row*64 + (cb ^ ((row & 7) << 2))] =
                    make_uint4(tf32u(v.x), tf32u(v.y), tf32u(v.z), tf32u(v.w));
            }
        }
        __syncthreads();

        #pragma unroll
        for (int ks = 0; ks < 8; ks++) {
            const int k0 = ks * 8;
            unsigned a[2][4], b[4][2];
            #pragma unroll
            for (int mt = 0; mt < 2; mt++) {
                const int base = (mw*32 + mt*16 + r4) * 64;
                a[mt][0] = As[base       + ((k0 + c4)     ^ swz)];
                a[mt][1] = As[base + 512 + ((k0 + c4)     ^ swz)];
                a[mt][2] = As[base       + ((k0 + c4 + 4) ^ swz)];
                a[mt][3] = As[base + 512 + ((k0 + c4 + 4) ^ swz)];
            }
            #pragma unroll
            for (int nt = 0; nt < 4; nt++) {
                const int base = (nw*32 + nt*8 + r4) * 64;
                b[nt][0] = Bs[base + ((k0 + c4)     ^ swz)];
                b[nt][1] = Bs[base + ((k0 + c4 + 4) ^ swz)];
            }
            #pragma unroll
            for (int mt = 0; mt < 2; mt++)
                #pragma unroll
                for (int nt = 0; nt < 4; nt++)
                    MMA_TF32(acc[mt][nt], a[mt], b[nt]);
        }
    }

    #pragma unroll
    for (int mt = 0; mt < 2; mt++) {
        const int ro = m0 + mw*32 + mt*16 + r4;
        #pragma unroll
        for (int nt = 0; nt < 4; nt++) {
            const int co = n0 + nw*32 + nt*8 + c4*2;
            const float b0 = __ldg(bo + co), b1 = __ldg(bo + co + 1);
            *(float2*)(out + (size_t)ro*NE + co) =
                make_float2(acc[mt][nt][0] + b0, acc[mt][nt][1] + b1);
            *(float2*)(out + (size_t)(ro + 8)*NE + co) =
                make_float2(acc[mt][nt][2] + b0, acc[mt][nt][3] + b1);
        }
    }
}

// ---------------------------------------------------------------------------
extern "C" void kernel_launch(void* const* d_in, const int* in_sizes, int n_in,
                              void* d_out, int out_size)
{
    const float* x    = (const float*)d_in[0];
    const int*   mask = (const int*)  d_in[1];
    const float* Wq   = (const float*)d_in[2];
    const float* Wk   = (const float*)d_in[3];
    const float* Wv   = (const float*)d_in[4];
    const float* Er   = (const float*)d_in[5];
    const float* Wo   = (const float*)d_in[6];
    const float* bo   = (const float*)d_in[7];
    float* out = (float*)d_out;

    cudaFuncSetAttribute(attn_tc_kernel,
                         cudaFuncAttributeMaxDynamicSharedMemorySize, 114688);

    proj_tf32_kernel<<<512, 256>>>(x, Wq, Wk, Wv);
    vmean_kernel<<<64, 256>>>();
    qer_tf32_kernel<<<dim3(16, 8, 64), 256>>>(Er);
    attn_tc_kernel<<<dim3(8, 64), 256, 114688>>>(mask);
    out_tf32_kernel<<<dim3(16, 32), 256>>>(Wo, bo, out);
}